// round 7
// baseline (speedup 1.0000x reference)
#include <cuda_runtime.h>
#include <cuda_bf16.h>
#include <cstdint>

#define N_NODES   50000
#define PAD_NODES 50048          // 782 * 64
#define N_EDGES   500000
#define DIM       128
#define N_GRAPHS  256
#define SCAN_N    (N_NODES + 1)

// ---------------- scratch (device globals: allocation-free, zero-init) ----------------
__device__ __align__(16) float g_m[N_NODES * DIM];   // messages  h @ W_rel^T
__device__ __align__(16) float g_r[N_NODES * DIM];   // root + bias (per layer, reused)
__device__ __align__(16) __nv_bfloat16 g_ahi[PAD_NODES * DIM];  // A hi (pad rows stay 0)
__device__ __align__(16) __nv_bfloat16 g_alo[PAD_NODES * DIM];  // A lo
__device__ __align__(16) __nv_bfloat16 g_whi[2][256 * DIM];     // W hi: rows 0-127 rel, 128-255 root
__device__ __align__(16) __nv_bfloat16 g_wlo[2][256 * DIM];     // W lo
__device__ int g_cnt[N_GRAPHS];
__device__ int g_is64;
// CSR (by destination)
__device__ int g_rowptr[SCAN_N];
__device__ int g_cursor[N_NODES];
__device__ int g_srcs[N_EDGES];

// ---------------- helpers ----------------
__device__ __forceinline__ uint32_t smem_u32(const void* p) {
    uint32_t a;
    asm("{ .reg .u64 t; cvta.to.shared.u64 t, %1; cvt.u32.u64 %0, t; }" : "=r"(a) : "l"(p));
    return a;
}
__device__ __forceinline__ int ld_idx(const void* p, long long i, int is64) {
    if (is64) return (int)((const long long*)p)[i];
    return ((const int*)p)[i];
}

// split 4 floats -> bf16 hi/lo packed as 2x uint2
__device__ __forceinline__ void split4(float4 v, uint2& hi, uint2& lo) {
    __nv_bfloat16 hx = __float2bfloat16_rn(v.x), hy = __float2bfloat16_rn(v.y);
    __nv_bfloat16 hz = __float2bfloat16_rn(v.z), hw = __float2bfloat16_rn(v.w);
    __nv_bfloat162 h0; h0.x = hx; h0.y = hy;
    __nv_bfloat162 h1; h1.x = hz; h1.y = hw;
    __nv_bfloat162 l0 = __floats2bfloat162_rn(v.x - __bfloat162float(hx),
                                              v.y - __bfloat162float(hy));
    __nv_bfloat162 l1 = __floats2bfloat162_rn(v.z - __bfloat162float(hz),
                                              v.w - __bfloat162float(hw));
    hi.x = *reinterpret_cast<uint32_t*>(&h0); hi.y = *reinterpret_cast<uint32_t*>(&h1);
    lo.x = *reinterpret_cast<uint32_t*>(&l0); lo.y = *reinterpret_cast<uint32_t*>(&l1);
}

// ---------------- side stream: convert x + all weights ----------------
__global__ __launch_bounds__(256) void cvt_all_kernel(
    const float* __restrict__ x,
    const float* __restrict__ W1rel, const float* __restrict__ W1root,
    const float* __restrict__ W2rel, const float* __restrict__ W2root)
{
    int t = blockIdx.x * blockDim.x + threadIdx.x;
    const int nx = N_NODES * DIM / 4;              // 1,600,000
    if (t < nx) {
        float4 v = *(const float4*)(x + (size_t)t * 4);
        uint2 hi, lo; split4(v, hi, lo);
        *(uint2*)(&g_ahi[(size_t)t * 4]) = hi;
        *(uint2*)(&g_alo[(size_t)t * 4]) = lo;
    }
    if (t < 4 * 128 * DIM / 4) {                   // 16384 weight threads
        int mat = t / (128 * DIM / 4);
        int off = (t % (128 * DIM / 4)) * 4;
        const float* src = (mat == 0) ? W1rel : (mat == 1) ? W1root
                         : (mat == 2) ? W2rel : W2root;
        int layer = mat >> 1;
        int half = mat & 1;                        // 0 rel -> rows 0-127, 1 root -> 128-255
        float4 v = *(const float4*)(src + off);
        uint2 hi, lo; split4(v, hi, lo);
        size_t dsto = (size_t)half * 128 * DIM + off;
        *(uint2*)(&g_whi[layer][dsto]) = hi;
        *(uint2*)(&g_wlo[layer][dsto]) = lo;
    }
}

// ---------------- main stream: detect + zero + init ----------------
__global__ void init_kernel(const unsigned* __restrict__ ew,
                            float* __restrict__ out, const float* __restrict__ b_out) {
    int i = blockIdx.x * blockDim.x + threadIdx.x;
    if (i == 0) {
        unsigned o = 0;
#pragma unroll
        for (int k = 1; k < 64; k += 2) o |= ew[k];
        g_is64 = (o == 0) ? 1 : 0;
    }
    if (i < SCAN_N) g_rowptr[i] = 0;
    if (i < N_GRAPHS) { g_cnt[i] = 0; out[i] = b_out[0]; }
}
__global__ void hist_count_kernel(const void* __restrict__ edges, const void* __restrict__ batch) {
    int e = blockIdx.x * blockDim.x + threadIdx.x;
    int is64 = g_is64;
    if (e < N_EDGES) {
        int dst = ld_idx(edges, (long long)N_EDGES + e, is64);
        atomicAdd(&g_rowptr[dst + 1], 1);
    }
    if (e < N_NODES) atomicAdd(&g_cnt[ld_idx(batch, e, is64)], 1);
}
// single-block two-pass inclusive scan of g_rowptr; seeds g_cursor with row starts
__global__ __launch_bounds__(1024) void scan_kernel() {
    __shared__ int ssum[1024];
    const int t = threadIdx.x;
    const int CH = 49;                      // 1024*49 = 50176 >= 50001
    const int base = t * CH;
    int s = 0;
#pragma unroll 7
    for (int i = 0; i < CH; i++) {
        int idx = base + i;
        if (idx < SCAN_N) s += g_rowptr[idx];
    }
    ssum[t] = s;
    __syncthreads();
#pragma unroll
    for (int off = 1; off < 1024; off <<= 1) {
        int v = (t >= off) ? ssum[t - off] : 0;
        __syncthreads();
        ssum[t] += v;
        __syncthreads();
    }
    int run = (t > 0) ? ssum[t - 1] : 0;
#pragma unroll 7
    for (int i = 0; i < CH; i++) {
        int idx = base + i;
        if (idx < SCAN_N) {
            run += g_rowptr[idx];
            g_rowptr[idx] = run;
            if (idx < N_NODES) g_cursor[idx] = run;
        }
    }
}
__global__ void fill_kernel(const void* __restrict__ edges) {
    int e = blockIdx.x * blockDim.x + threadIdx.x;
    if (e < N_EDGES) {
        int is64 = g_is64;
        int src = ld_idx(edges, e, is64);
        int dst = ld_idx(edges, (long long)N_EDGES + e, is64);
        int pos = atomicAdd(&g_cursor[dst], 1);
        g_srcs[pos] = src;
    }
}

// ---------------- mma.sync bf16 GEMM (64x128 tile, 2 CTAs/SM, preconverted inputs) ----------------
#define PITCH_B 272
#define A_SZ    (64 * PITCH_B)             // 17408
#define B_SZ    (128 * PITCH_B)            // 34816
#define SMEM_BYTES (2 * A_SZ + 2 * B_SZ)   // 104448

__device__ __forceinline__ void ldsm_x4(uint32_t* r, uint32_t addr) {
    asm volatile("ldmatrix.sync.aligned.m8n8.x4.shared.b16 {%0,%1,%2,%3}, [%4];"
                 : "=r"(r[0]), "=r"(r[1]), "=r"(r[2]), "=r"(r[3]) : "r"(addr));
}
__device__ __forceinline__ void mma16816(float* d, const uint32_t* a, const uint32_t* b) {
    asm volatile(
        "mma.sync.aligned.m16n8k16.row.col.f32.bf16.bf16.f32 "
        "{%0,%1,%2,%3}, {%4,%5,%6,%7}, {%8,%9}, {%0,%1,%2,%3};"
        : "+f"(d[0]), "+f"(d[1]), "+f"(d[2]), "+f"(d[3])
        : "r"(a[0]), "r"(a[1]), "r"(a[2]), "r"(a[3]), "r"(b[0]), "r"(b[1]));
}
__device__ __forceinline__ void sts128u(uint32_t addr, uint4 v) {
    asm volatile("st.shared.v4.b32 [%0], {%1,%2,%3,%4};"
                 :: "r"(addr), "r"(v.x), "r"(v.y), "r"(v.z), "r"(v.w) : "memory");
}

__global__ __launch_bounds__(256, 2) void gemm_mma(
    const __nv_bfloat16* __restrict__ Whi, const __nv_bfloat16* __restrict__ Wlo,
    const float* __restrict__ bias,
    float* __restrict__ OutRel, float* __restrict__ OutRoot)
{
    extern __shared__ char smem[];
    const uint32_t sA = smem_u32(smem);            // A hi, A lo
    const uint32_t sB = sA + 2 * A_SZ;             // B hi, B lo
    const int tid = threadIdx.x;
    const int wid = tid >> 5;
    const int lane = tid & 31;
    const int row0 = blockIdx.x * 64;
    const bool isRoot = (blockIdx.y == 1);

    const __nv_bfloat16* __restrict__ Bh = Whi + (size_t)(isRoot ? 128 : 0) * DIM;
    const __nv_bfloat16* __restrict__ Bl = Wlo + (size_t)(isRoot ? 128 : 0) * DIM;
    float* __restrict__ Out = isRoot ? OutRoot : OutRel;

    // ---- A tile: 64 rows x 128 bf16 (hi & lo), pure copy ----
#pragma unroll
    for (int i = 0; i < 4; i++) {
        int g = tid + i * 256;                 // 0..1023
        int row = g >> 4;                      // 0..63
        int v = g & 15;                        // uint4 index within row
        size_t srco = (size_t)(row0 + row) * DIM + v * 8;
        uint32_t off = (uint32_t)(row * PITCH_B + v * 16);
        sts128u(sA + off,        *(const uint4*)(g_ahi + srco));
        sts128u(sA + A_SZ + off, *(const uint4*)(g_alo + srco));
    }
    // ---- B: 128 rows x 128 bf16 (hi & lo) ----
#pragma unroll
    for (int i = 0; i < 8; i++) {
        int g = tid + i * 256;                 // 0..2047
        int row = g >> 4;                      // 0..127
        int v = g & 15;
        size_t srco = (size_t)row * DIM + v * 8;
        uint32_t off = (uint32_t)(row * PITCH_B + v * 16);
        sts128u(sB + off,        *(const uint4*)(Bh + srco));
        sts128u(sB + B_SZ + off, *(const uint4*)(Bl + srco));
    }
    __syncthreads();

    // ---- warp tiling: 2 (M) x 4 (N); warp tile 32x32 ----
    const int wm = wid >> 2;
    const int wn = wid & 3;
    const int t4 = lane >> 2;
    const int t2 = (lane & 3) * 2;

    float d[2][4][4];
#pragma unroll
    for (int i = 0; i < 2; i++)
#pragma unroll
        for (int j = 0; j < 4; j++)
#pragma unroll
            for (int q = 0; q < 4; q++) d[i][j][q] = 0.f;

    const uint32_t aRowOff = (uint32_t)((lane & 15) * PITCH_B + (lane >> 4) * 16);
    const uint32_t bRowOff = (uint32_t)((wn * 32 + (lane & 7) + (lane >> 4) * 8) * PITCH_B
                                        + ((lane >> 3) & 1) * 16);

    const int paA[3] = {0, 1, 0};
    const int paB[3] = {0, 0, 1};
#pragma unroll
    for (int p = 0; p < 3; p++) {
        const uint32_t Ab = sA + paA[p] * A_SZ;
        const uint32_t Bb = sB + paB[p] * B_SZ;
#pragma unroll
        for (int ks = 0; ks < 8; ks++) {
            uint32_t a[2][4];
#pragma unroll
            for (int i = 0; i < 2; i++)
                ldsm_x4(a[i], Ab + (uint32_t)((wm * 32 + i * 16) * PITCH_B + ks * 32) + aRowOff);
            uint32_t bf[4][2];
#pragma unroll
            for (int jp = 0; jp < 2; jp++) {
                uint32_t r[4];
                ldsm_x4(r, Bb + (uint32_t)(jp * 16 * PITCH_B + ks * 32) + bRowOff);
                bf[jp * 2 + 0][0] = r[0]; bf[jp * 2 + 0][1] = r[1];
                bf[jp * 2 + 1][0] = r[2]; bf[jp * 2 + 1][1] = r[3];
            }
#pragma unroll
            for (int i = 0; i < 2; i++)
#pragma unroll
                for (int j = 0; j < 4; j++)
                    mma16816(d[i][j], a[i], bf[j]);
        }
    }

    // ---- epilogue ----
#pragma unroll
    for (int i = 0; i < 2; i++) {
#pragma unroll
        for (int half = 0; half < 2; half++) {
            int grow = row0 + wm * 32 + i * 16 + t4 + half * 8;
            if (grow >= N_NODES) continue;
#pragma unroll
            for (int j = 0; j < 4; j++) {
                int col = wn * 32 + j * 8 + t2;
                float2 v = make_float2(d[i][j][half * 2], d[i][j][half * 2 + 1]);
                if (isRoot) { v.x += bias[col]; v.y += bias[col + 1]; }
                *(float2*)(Out + (size_t)grow * DIM + col) = v;
            }
        }
    }
}

// ---------------- agg1: h1 = relu(root + sum msgs); emit bf16 hi/lo for gemm2 ----------------
__global__ __launch_bounds__(256) void agg1_kernel() {
    int node = (blockIdx.x * blockDim.x + threadIdx.x) >> 5;
    if (node >= N_NODES) return;
    const int lane = threadIdx.x & 31;
    const float4* __restrict__ M = (const float4*)g_m;
    int s = g_rowptr[node], e = g_rowptr[node + 1];
    float4 acc = make_float4(0.f, 0.f, 0.f, 0.f);
    for (int j = s; j < e; j++) {
        int src = g_srcs[j];
        float4 v = M[(size_t)src * 32 + lane];
        acc.x += v.x; acc.y += v.y; acc.z += v.z; acc.w += v.w;
    }
    float4 r = ((const float4*)g_r)[(size_t)node * 32 + lane];
    r.x = fmaxf(r.x + acc.x, 0.f); r.y = fmaxf(r.y + acc.y, 0.f);
    r.z = fmaxf(r.z + acc.z, 0.f); r.w = fmaxf(r.w + acc.w, 0.f);
    uint2 hi, lo; split4(r, hi, lo);
    ((uint2*)g_ahi)[(size_t)node * 32 + lane] = hi;
    ((uint2*)g_alo)[(size_t)node * 32 + lane] = lo;
}

// ---------------- layer-2 aggregate fused with mean-pool + head ----------------
__global__ __launch_bounds__(256) void agg2_pool_kernel(const void* __restrict__ batch,
                                                        const float* __restrict__ Wout,
                                                        float* __restrict__ out) {
    int node = (blockIdx.x * blockDim.x + threadIdx.x) >> 5;
    if (node >= N_NODES) return;
    const int lane = threadIdx.x & 31;
    const float4* __restrict__ M = (const float4*)g_m;
    int s = g_rowptr[node], e = g_rowptr[node + 1];
    float4 acc = make_float4(0.f, 0.f, 0.f, 0.f);
    for (int j = s; j < e; j++) {
        int src = g_srcs[j];
        float4 v = M[(size_t)src * 32 + lane];
        acc.x += v.x; acc.y += v.y; acc.z += v.z; acc.w += v.w;
    }
    float4 r = ((const float4*)g_r)[(size_t)node * 32 + lane];
    r.x = fmaxf(r.x + acc.x, 0.f); r.y = fmaxf(r.y + acc.y, 0.f);
    r.z = fmaxf(r.z + acc.z, 0.f); r.w = fmaxf(r.w + acc.w, 0.f);
    float4 w = ((const float4*)Wout)[lane];
    float sdot = r.x * w.x + r.y * w.y + r.z * w.z + r.w * w.w;
#pragma unroll
    for (int o = 16; o; o >>= 1) sdot += __shfl_xor_sync(0xffffffffu, sdot, o);
    if (lane == 0) {
        int gidx = ld_idx(batch, node, g_is64);
        int c = g_cnt[gidx]; if (c < 1) c = 1;
        atomicAdd(&out[gidx], sdot / (float)c);
    }
}

// ---------------- launcher ----------------
extern "C" void kernel_launch(void* const* d_in, const int* in_sizes, int n_in,
                              void* d_out, int out_size) {
    const float* x       = (const float*)d_in[0];
    const void*  edges   = d_in[1];
    const void*  batch   = d_in[2];
    const float* W1_rel  = (const float*)d_in[3];
    const float* W1_root = (const float*)d_in[4];
    const float* b1      = (const float*)d_in[5];
    const float* W2_rel  = (const float*)d_in[6];
    const float* W2_root = (const float*)d_in[7];
    const float* b2      = (const float*)d_in[8];
    const float* W_out   = (const float*)d_in[9];
    const float* b_out   = (const float*)d_in[10];
    float* out = (float*)d_out;

    // lazily-created side stream + fork/join events (handles only; no device work
    // or memory; identical GPU work on every call)
    static cudaStream_t s1 = nullptr;
    static cudaEvent_t evFork = nullptr, evJoin = nullptr;
    if (!s1) {
        cudaStreamCreateWithFlags(&s1, cudaStreamNonBlocking);
        cudaEventCreateWithFlags(&evFork, cudaEventDisableTiming);
        cudaEventCreateWithFlags(&evJoin, cudaEventDisableTiming);
    }

    cudaFuncSetAttribute(gemm_mma, cudaFuncAttributeMaxDynamicSharedMemorySize, SMEM_BYTES);

    const dim3 gemmGrid(PAD_NODES / 64, 2);          // (782, 2)
    const int aggBlks = (N_NODES * 32 + 255) / 256;  // warp per node

    float *pm, *pr;
    cudaGetSymbolAddress((void**)&pm, g_m);
    cudaGetSymbolAddress((void**)&pr, g_r);
    __nv_bfloat16 *pwh, *pwl;
    cudaGetSymbolAddress((void**)&pwh, g_whi);
    cudaGetSymbolAddress((void**)&pwl, g_wlo);

    // ---- fork: side stream does feature/weight conversion + layer-1 GEMM ----
    cudaEventRecord(evFork, 0);
    cudaStreamWaitEvent(s1, evFork, 0);
    cvt_all_kernel<<<(N_NODES * DIM / 4 + 255) / 256, 256, 0, s1>>>(
        x, W1_rel, W1_root, W2_rel, W2_root);
    gemm_mma<<<gemmGrid, 256, SMEM_BYTES, s1>>>(pwh, pwl, b1, pm, pr);
    cudaEventRecord(evJoin, s1);

    // ---- main stream: CSR build ----
    init_kernel<<<(SCAN_N + 255) / 256, 256>>>((const unsigned*)edges, out, b_out);
    hist_count_kernel<<<(N_EDGES + 255) / 256, 256>>>(edges, batch);
    scan_kernel<<<1, 1024>>>();
    fill_kernel<<<(N_EDGES + 255) / 256, 256>>>(edges);

    // ---- join, then layer 1 aggregate -> layer 2 ----
    cudaStreamWaitEvent(0, evJoin, 0);
    agg1_kernel<<<aggBlks, 256>>>();
    gemm_mma<<<gemmGrid, 256, SMEM_BYTES>>>(pwh + 256 * DIM, pwl + 256 * DIM, b2, pm, pr);
    agg2_pool_kernel<<<aggBlks, 256>>>(batch, W_out, out);
}

// round 8
// speedup vs baseline: 1.4220x; 1.4220x over previous
#include <cuda_runtime.h>
#include <cuda_bf16.h>
#include <cstdint>

#define N_NODES   50000
#define PAD_NODES 50048          // 782 * 64
#define N_EDGES   500000
#define DIM       128
#define N_GRAPHS  256
#define SCAN_N    (N_NODES + 1)

// ---------------- scratch (device globals: allocation-free, zero-init) ----------------
__device__ __align__(16) float g_m[N_NODES * DIM];   // messages  h @ W_rel^T
__device__ __align__(16) float g_r[N_NODES * DIM];   // root + bias (per layer, reused)
__device__ __align__(16) __nv_bfloat16 g_ahi[PAD_NODES * DIM];  // h1 bf16 hi (pad rows stay 0)
__device__ __align__(16) __nv_bfloat16 g_alo[PAD_NODES * DIM];  // h1 bf16 lo
__device__ int g_cnt[N_GRAPHS];
__device__ int g_is64;
// CSR (by destination)
__device__ int g_rowptr[SCAN_N];
__device__ int g_cursor[N_NODES];
__device__ int g_srcs[N_EDGES];

// ---------------- helpers ----------------
__device__ __forceinline__ uint32_t smem_u32(const void* p) {
    uint32_t a;
    asm("{ .reg .u64 t; cvta.to.shared.u64 t, %1; cvt.u32.u64 %0, t; }" : "=r"(a) : "l"(p));
    return a;
}
__device__ __forceinline__ int ld_idx(const void* p, long long i, int is64) {
    if (is64) return (int)((const long long*)p)[i];
    return ((const int*)p)[i];
}

// split 4 floats -> bf16 hi/lo packed as 2x uint2
__device__ __forceinline__ void split4(float4 v, uint2& hi, uint2& lo) {
    __nv_bfloat16 hx = __float2bfloat16_rn(v.x), hy = __float2bfloat16_rn(v.y);
    __nv_bfloat16 hz = __float2bfloat16_rn(v.z), hw = __float2bfloat16_rn(v.w);
    __nv_bfloat162 h0; h0.x = hx; h0.y = hy;
    __nv_bfloat162 h1; h1.x = hz; h1.y = hw;
    __nv_bfloat162 l0 = __floats2bfloat162_rn(v.x - __bfloat162float(hx),
                                              v.y - __bfloat162float(hy));
    __nv_bfloat162 l1 = __floats2bfloat162_rn(v.z - __bfloat162float(hz),
                                              v.w - __bfloat162float(hw));
    hi.x = *reinterpret_cast<uint32_t*>(&h0); hi.y = *reinterpret_cast<uint32_t*>(&h1);
    lo.x = *reinterpret_cast<uint32_t*>(&l0); lo.y = *reinterpret_cast<uint32_t*>(&l1);
}
__device__ __forceinline__ void cvt8(float4 v0, float4 v1, uint4& hi, uint4& lo) {
    uint2 h0, l0, h1, l1;
    split4(v0, h0, l0);
    split4(v1, h1, l1);
    hi = make_uint4(h0.x, h0.y, h1.x, h1.y);
    lo = make_uint4(l0.x, l0.y, l1.x, l1.y);
}

// ---------------- init: detect + zero rowptr + cnt/out ----------------
__global__ void init_kernel(const unsigned* __restrict__ ew,
                            float* __restrict__ out, const float* __restrict__ b_out) {
    int i = blockIdx.x * blockDim.x + threadIdx.x;
    if (i == 0) {
        unsigned o = 0;
#pragma unroll
        for (int k = 1; k < 64; k += 2) o |= ew[k];
        g_is64 = (o == 0) ? 1 : 0;
    }
    if (i < SCAN_N) g_rowptr[i] = 0;
    if (i < N_GRAPHS) { g_cnt[i] = 0; out[i] = b_out[0]; }
}
__global__ void hist_count_kernel(const void* __restrict__ edges, const void* __restrict__ batch) {
    int e = blockIdx.x * blockDim.x + threadIdx.x;
    int is64 = g_is64;
    if (e < N_EDGES) {
        int dst = ld_idx(edges, (long long)N_EDGES + e, is64);
        atomicAdd(&g_rowptr[dst + 1], 1);
    }
    if (e < N_NODES) atomicAdd(&g_cnt[ld_idx(batch, e, is64)], 1);
}
// single-block two-pass inclusive scan of g_rowptr; seeds g_cursor with row starts
__global__ __launch_bounds__(1024) void scan_kernel() {
    __shared__ int ssum[1024];
    const int t = threadIdx.x;
    const int CH = 49;                      // 1024*49 = 50176 >= 50001
    const int base = t * CH;
    int s = 0;
#pragma unroll 7
    for (int i = 0; i < CH; i++) {
        int idx = base + i;
        if (idx < SCAN_N) s += g_rowptr[idx];
    }
    ssum[t] = s;
    __syncthreads();
#pragma unroll
    for (int off = 1; off < 1024; off <<= 1) {
        int v = (t >= off) ? ssum[t - off] : 0;
        __syncthreads();
        ssum[t] += v;
        __syncthreads();
    }
    int run = (t > 0) ? ssum[t - 1] : 0;
#pragma unroll 7
    for (int i = 0; i < CH; i++) {
        int idx = base + i;
        if (idx < SCAN_N) {
            run += g_rowptr[idx];
            g_rowptr[idx] = run;
            if (idx < N_NODES) g_cursor[idx] = run;
        }
    }
}
__global__ void fill_kernel(const void* __restrict__ edges) {
    int e = blockIdx.x * blockDim.x + threadIdx.x;
    if (e < N_EDGES) {
        int is64 = g_is64;
        int src = ld_idx(edges, e, is64);
        int dst = ld_idx(edges, (long long)N_EDGES + e, is64);
        int pos = atomicAdd(&g_cursor[dst], 1);
        g_srcs[pos] = src;
    }
}

// ---------------- mma.sync bf16 GEMM (64x128 tile, 2 CTAs/SM) ----------------
// preA=0: A = fp32 Xin rows (convert in prologue). preA=1: A = g_ahi/g_alo copy.
// W always fp32, converted in prologue. blockIdx.y: 0 -> Wrel -> g_m, 1 -> Wroot+bias -> g_r.
#define PITCH_B 272
#define A_SZ    (64 * PITCH_B)             // 17408
#define B_SZ    (128 * PITCH_B)            // 34816
#define SMEM_BYTES (2 * A_SZ + 2 * B_SZ)   // 104448

__device__ __forceinline__ void ldsm_x4(uint32_t* r, uint32_t addr) {
    asm volatile("ldmatrix.sync.aligned.m8n8.x4.shared.b16 {%0,%1,%2,%3}, [%4];"
                 : "=r"(r[0]), "=r"(r[1]), "=r"(r[2]), "=r"(r[3]) : "r"(addr));
}
__device__ __forceinline__ void mma16816(float* d, const uint32_t* a, const uint32_t* b) {
    asm volatile(
        "mma.sync.aligned.m16n8k16.row.col.f32.bf16.bf16.f32 "
        "{%0,%1,%2,%3}, {%4,%5,%6,%7}, {%8,%9}, {%0,%1,%2,%3};"
        : "+f"(d[0]), "+f"(d[1]), "+f"(d[2]), "+f"(d[3])
        : "r"(a[0]), "r"(a[1]), "r"(a[2]), "r"(a[3]), "r"(b[0]), "r"(b[1]));
}
__device__ __forceinline__ void sts128u(uint32_t addr, uint4 v) {
    asm volatile("st.shared.v4.b32 [%0], {%1,%2,%3,%4};"
                 :: "r"(addr), "r"(v.x), "r"(v.y), "r"(v.z), "r"(v.w) : "memory");
}

__global__ __launch_bounds__(256, 2) void gemm_mma(
    const float* __restrict__ Xin, int preA,
    const float* __restrict__ Wrel, const float* __restrict__ Wroot,
    const float* __restrict__ bias)
{
    extern __shared__ char smem[];
    const uint32_t sA = smem_u32(smem);            // A hi, A lo
    const uint32_t sB = sA + 2 * A_SZ;             // B hi, B lo
    const int tid = threadIdx.x;
    const int wid = tid >> 5;
    const int lane = tid & 31;
    const int row0 = blockIdx.x * 64;
    const bool isRoot = (blockIdx.y == 1);

    const float* __restrict__ W = isRoot ? Wroot : Wrel;
    float* __restrict__ Out = isRoot ? g_r : g_m;

    // ---- A tile: 64 rows x 128 ----
    if (preA) {
#pragma unroll
        for (int i = 0; i < 4; i++) {
            int g = tid + i * 256;             // 0..1023
            int row = g >> 4;
            int v = g & 15;
            size_t srco = (size_t)(row0 + row) * DIM + v * 8;
            uint32_t off = (uint32_t)(row * PITCH_B + v * 16);
            sts128u(sA + off,        *(const uint4*)(g_ahi + srco));
            sts128u(sA + A_SZ + off, *(const uint4*)(g_alo + srco));
        }
    } else {
#pragma unroll
        for (int i = 0; i < 4; i++) {
            int g = tid + i * 256;
            int row = g >> 4;                  // 0..63
            int e0 = (g & 15) * 8;
            int grow = row0 + row;
            float4 v0 = make_float4(0.f, 0.f, 0.f, 0.f), v1 = v0;
            if (grow < N_NODES) {
                v0 = *(const float4*)(Xin + (size_t)grow * DIM + e0);
                v1 = *(const float4*)(Xin + (size_t)grow * DIM + e0 + 4);
            }
            uint4 hi, lo; cvt8(v0, v1, hi, lo);
            uint32_t off = (uint32_t)(row * PITCH_B + e0 * 2);
            sts128u(sA + off, hi);
            sts128u(sA + A_SZ + off, lo);
        }
    }
    // ---- B: full W 128 x 128, convert ----
#pragma unroll
    for (int i = 0; i < 8; i++) {
        int g = tid + i * 256;                 // 0..2047
        int row = g >> 4;                      // 0..127
        int e0 = (g & 15) * 8;
        float4 w0 = *(const float4*)(W + (size_t)row * DIM + e0);
        float4 w1 = *(const float4*)(W + (size_t)row * DIM + e0 + 4);
        uint4 whi, wlo; cvt8(w0, w1, whi, wlo);
        uint32_t off = (uint32_t)(row * PITCH_B + e0 * 2);
        sts128u(sB + off, whi);
        sts128u(sB + B_SZ + off, wlo);
    }
    __syncthreads();

    // ---- warp tiling: 2 (M) x 4 (N); warp tile 32x32 ----
    const int wm = wid >> 2;
    const int wn = wid & 3;
    const int t4 = lane >> 2;
    const int t2 = (lane & 3) * 2;

    float d[2][4][4];
#pragma unroll
    for (int i = 0; i < 2; i++)
#pragma unroll
        for (int j = 0; j < 4; j++)
#pragma unroll
            for (int q = 0; q < 4; q++) d[i][j][q] = 0.f;

    const uint32_t aRowOff = (uint32_t)((lane & 15) * PITCH_B + (lane >> 4) * 16);
    const uint32_t bRowOff = (uint32_t)((wn * 32 + (lane & 7) + (lane >> 4) * 8) * PITCH_B
                                        + ((lane >> 3) & 1) * 16);

    const int paA[3] = {0, 1, 0};
    const int paB[3] = {0, 0, 1};
#pragma unroll
    for (int p = 0; p < 3; p++) {
        const uint32_t Ab = sA + paA[p] * A_SZ;
        const uint32_t Bb = sB + paB[p] * B_SZ;
#pragma unroll
        for (int ks = 0; ks < 8; ks++) {
            uint32_t a[2][4];
#pragma unroll
            for (int i = 0; i < 2; i++)
                ldsm_x4(a[i], Ab + (uint32_t)((wm * 32 + i * 16) * PITCH_B + ks * 32) + aRowOff);
            uint32_t bf[4][2];
#pragma unroll
            for (int jp = 0; jp < 2; jp++) {
                uint32_t r[4];
                ldsm_x4(r, Bb + (uint32_t)(jp * 16 * PITCH_B + ks * 32) + bRowOff);
                bf[jp * 2 + 0][0] = r[0]; bf[jp * 2 + 0][1] = r[1];
                bf[jp * 2 + 1][0] = r[2]; bf[jp * 2 + 1][1] = r[3];
            }
#pragma unroll
            for (int i = 0; i < 2; i++)
#pragma unroll
                for (int j = 0; j < 4; j++)
                    mma16816(d[i][j], a[i], bf[j]);
        }
    }

    // ---- epilogue ----
#pragma unroll
    for (int i = 0; i < 2; i++) {
#pragma unroll
        for (int half = 0; half < 2; half++) {
            int grow = row0 + wm * 32 + i * 16 + t4 + half * 8;
            if (grow >= N_NODES) continue;
#pragma unroll
            for (int j = 0; j < 4; j++) {
                int col = wn * 32 + j * 8 + t2;
                float2 v = make_float2(d[i][j][half * 2], d[i][j][half * 2 + 1]);
                if (isRoot) { v.x += bias[col]; v.y += bias[col + 1]; }
                *(float2*)(Out + (size_t)grow * DIM + col) = v;
            }
        }
    }
}

// ---------------- agg1: h1 = relu(root + sum msgs) -> bf16 hi/lo for gemm2 ----------------
__global__ __launch_bounds__(256) void agg1_kernel() {
    int node = (blockIdx.x * blockDim.x + threadIdx.x) >> 5;
    if (node >= N_NODES) return;
    const int lane = threadIdx.x & 31;
    const float4* __restrict__ M = (const float4*)g_m;
    int s = g_rowptr[node], e = g_rowptr[node + 1];
    float4 acc = make_float4(0.f, 0.f, 0.f, 0.f);
    for (int j = s; j < e; j++) {
        int src = g_srcs[j];
        float4 v = M[(size_t)src * 32 + lane];
        acc.x += v.x; acc.y += v.y; acc.z += v.z; acc.w += v.w;
    }
    float4 r = ((const float4*)g_r)[(size_t)node * 32 + lane];
    r.x = fmaxf(r.x + acc.x, 0.f); r.y = fmaxf(r.y + acc.y, 0.f);
    r.z = fmaxf(r.z + acc.z, 0.f); r.w = fmaxf(r.w + acc.w, 0.f);
    uint2 hi, lo; split4(r, hi, lo);
    ((uint2*)g_ahi)[(size_t)node * 32 + lane] = hi;
    ((uint2*)g_alo)[(size_t)node * 32 + lane] = lo;
}

// ---------------- layer-2 aggregate fused with mean-pool + head ----------------
__global__ __launch_bounds__(256) void agg2_pool_kernel(const void* __restrict__ batch,
                                                        const float* __restrict__ Wout,
                                                        float* __restrict__ out) {
    int node = (blockIdx.x * blockDim.x + threadIdx.x) >> 5;
    if (node >= N_NODES) return;
    const int lane = threadIdx.x & 31;
    const float4* __restrict__ M = (const float4*)g_m;
    int s = g_rowptr[node], e = g_rowptr[node + 1];
    float4 acc = make_float4(0.f, 0.f, 0.f, 0.f);
    for (int j = s; j < e; j++) {
        int src = g_srcs[j];
        float4 v = M[(size_t)src * 32 + lane];
        acc.x += v.x; acc.y += v.y; acc.z += v.z; acc.w += v.w;
    }
    float4 r = ((const float4*)g_r)[(size_t)node * 32 + lane];
    r.x = fmaxf(r.x + acc.x, 0.f); r.y = fmaxf(r.y + acc.y, 0.f);
    r.z = fmaxf(r.z + acc.z, 0.f); r.w = fmaxf(r.w + acc.w, 0.f);
    float4 w = ((const float4*)Wout)[lane];
    float sdot = r.x * w.x + r.y * w.y + r.z * w.z + r.w * w.w;
#pragma unroll
    for (int o = 16; o; o >>= 1) sdot += __shfl_xor_sync(0xffffffffu, sdot, o);
    if (lane == 0) {
        int gidx = ld_idx(batch, node, g_is64);
        int c = g_cnt[gidx]; if (c < 1) c = 1;
        atomicAdd(&out[gidx], sdot / (float)c);
    }
}

// ---------------- launcher (single stream, 8 launches) ----------------
extern "C" void kernel_launch(void* const* d_in, const int* in_sizes, int n_in,
                              void* d_out, int out_size) {
    const float* x       = (const float*)d_in[0];
    const void*  edges   = d_in[1];
    const void*  batch   = d_in[2];
    const float* W1_rel  = (const float*)d_in[3];
    const float* W1_root = (const float*)d_in[4];
    const float* b1      = (const float*)d_in[5];
    const float* W2_rel  = (const float*)d_in[6];
    const float* W2_root = (const float*)d_in[7];
    const float* b2      = (const float*)d_in[8];
    const float* W_out   = (const float*)d_in[9];
    const float* b_out   = (const float*)d_in[10];
    float* out = (float*)d_out;

    cudaFuncSetAttribute(gemm_mma, cudaFuncAttributeMaxDynamicSharedMemorySize, SMEM_BYTES);

    const dim3 gemmGrid(PAD_NODES / 64, 2);          // (782, 2)
    const int aggBlks = (N_NODES * 32 + 255) / 256;  // warp per node

    init_kernel<<<(SCAN_N + 255) / 256, 256>>>((const unsigned*)edges, out, b_out);
    hist_count_kernel<<<(N_EDGES + 255) / 256, 256>>>(edges, batch);
    scan_kernel<<<1, 1024>>>();
    fill_kernel<<<(N_EDGES + 255) / 256, 256>>>(edges);

    gemm_mma<<<gemmGrid, 256, SMEM_BYTES>>>(x, 0, W1_rel, W1_root, b1);
    agg1_kernel<<<aggBlks, 256>>>();

    gemm_mma<<<gemmGrid, 256, SMEM_BYTES>>>(nullptr, 1, W2_rel, W2_root, b2);
    agg2_pool_kernel<<<aggBlks, 256>>>(batch, W_out, out);
}

// round 9
// speedup vs baseline: 1.8486x; 1.3000x over previous
#include <cuda_runtime.h>
#include <cuda_bf16.h>
#include <cstdint>

#define N_NODES   50000
#define PAD_NODES 50048          // 782 * 64
#define N_EDGES   500000
#define DIM       128
#define N_GRAPHS  256
#define SCAN_N    (N_NODES + 1)
#define SCAN_BLKS 49             // ceil(50001/1024)

// ---------------- scratch (device globals: allocation-free, zero-init) ----------------
__device__ __align__(16) float g_m[N_NODES * DIM];   // messages  h @ W_rel^T
__device__ __align__(16) float g_r[N_NODES * DIM];   // root + bias (per layer, reused)
__device__ __align__(16) __nv_bfloat16 g_ahi[PAD_NODES * DIM];  // h1 bf16 hi (pad rows stay 0)
__device__ __align__(16) __nv_bfloat16 g_alo[PAD_NODES * DIM];  // h1 bf16 lo
__device__ int g_cnt[N_GRAPHS];
__device__ int g_is64;
// CSR (by destination)
__device__ int g_rowptr[SCAN_N];
__device__ int g_cursor[N_NODES];
__device__ int g_srcs[N_EDGES];
__device__ int g_bsum[SCAN_BLKS];

// ---------------- helpers ----------------
__device__ __forceinline__ uint32_t smem_u32(const void* p) {
    uint32_t a;
    asm("{ .reg .u64 t; cvta.to.shared.u64 t, %1; cvt.u32.u64 %0, t; }" : "=r"(a) : "l"(p));
    return a;
}
__device__ __forceinline__ int ld_idx(const void* p, long long i, int is64) {
    if (is64) return (int)((const long long*)p)[i];
    return ((const int*)p)[i];
}

// split 4 floats -> bf16 hi/lo packed as 2x uint2
__device__ __forceinline__ void split4(float4 v, uint2& hi, uint2& lo) {
    __nv_bfloat16 hx = __float2bfloat16_rn(v.x), hy = __float2bfloat16_rn(v.y);
    __nv_bfloat16 hz = __float2bfloat16_rn(v.z), hw = __float2bfloat16_rn(v.w);
    __nv_bfloat162 h0; h0.x = hx; h0.y = hy;
    __nv_bfloat162 h1; h1.x = hz; h1.y = hw;
    __nv_bfloat162 l0 = __floats2bfloat162_rn(v.x - __bfloat162float(hx),
                                              v.y - __bfloat162float(hy));
    __nv_bfloat162 l1 = __floats2bfloat162_rn(v.z - __bfloat162float(hz),
                                              v.w - __bfloat162float(hw));
    hi.x = *reinterpret_cast<uint32_t*>(&h0); hi.y = *reinterpret_cast<uint32_t*>(&h1);
    lo.x = *reinterpret_cast<uint32_t*>(&l0); lo.y = *reinterpret_cast<uint32_t*>(&l1);
}
__device__ __forceinline__ void cvt8(float4 v0, float4 v1, uint4& hi, uint4& lo) {
    uint2 h0, l0, h1, l1;
    split4(v0, h0, l0);
    split4(v1, h1, l1);
    hi = make_uint4(h0.x, h0.y, h1.x, h1.y);
    lo = make_uint4(l0.x, l0.y, l1.x, l1.y);
}

// ---------------- init: detect + zero rowptr + cnt/out ----------------
__global__ void init_kernel(const unsigned* __restrict__ ew,
                            float* __restrict__ out, const float* __restrict__ b_out) {
    int i = blockIdx.x * blockDim.x + threadIdx.x;
    if (i == 0) {
        unsigned o = 0;
#pragma unroll
        for (int k = 1; k < 64; k += 2) o |= ew[k];
        g_is64 = (o == 0) ? 1 : 0;
    }
    if (i < SCAN_N) g_rowptr[i] = 0;
    if (i < N_GRAPHS) { g_cnt[i] = 0; out[i] = b_out[0]; }
}
__global__ void hist_count_kernel(const void* __restrict__ edges, const void* __restrict__ batch) {
    int e = blockIdx.x * blockDim.x + threadIdx.x;
    int is64 = g_is64;
    if (e < N_EDGES) {
        int dst = ld_idx(edges, (long long)N_EDGES + e, is64);
        atomicAdd(&g_rowptr[dst + 1], 1);
    }
    if (e < N_NODES) atomicAdd(&g_cnt[ld_idx(batch, e, is64)], 1);
}
// ---------------- 3-kernel scan (R5-proven) ----------------
__global__ __launch_bounds__(1024) void scan1_kernel() {
    __shared__ int sd[1024];
    int gid = blockIdx.x * 1024 + threadIdx.x;
    int v = (gid < SCAN_N) ? g_rowptr[gid] : 0;
    sd[threadIdx.x] = v;
    __syncthreads();
#pragma unroll
    for (int off = 1; off < 1024; off <<= 1) {
        int t = (threadIdx.x >= off) ? sd[threadIdx.x - off] : 0;
        __syncthreads();
        sd[threadIdx.x] += t;
        __syncthreads();
    }
    if (gid < SCAN_N) g_rowptr[gid] = sd[threadIdx.x];
    if (threadIdx.x == 1023) g_bsum[blockIdx.x] = sd[1023];
}
__global__ void scan2_kernel() {
    if (threadIdx.x == 0) {
        int run = 0;
        for (int i = 0; i < SCAN_BLKS; i++) { int t = g_bsum[i]; g_bsum[i] = run; run += t; }
    }
}
__global__ __launch_bounds__(1024) void scan3_kernel() {
    int gid = blockIdx.x * 1024 + threadIdx.x;
    if (gid < SCAN_N) {
        int v = g_rowptr[gid] + ((blockIdx.x > 0) ? g_bsum[blockIdx.x] : 0);
        if (blockIdx.x > 0) g_rowptr[gid] = v;
        if (gid < N_NODES) g_cursor[gid] = v;   // seed fill cursor with row start
    }
}
__global__ void fill_kernel(const void* __restrict__ edges) {
    int e = blockIdx.x * blockDim.x + threadIdx.x;
    if (e < N_EDGES) {
        int is64 = g_is64;
        int src = ld_idx(edges, e, is64);
        int dst = ld_idx(edges, (long long)N_EDGES + e, is64);
        int pos = atomicAdd(&g_cursor[dst], 1);
        g_srcs[pos] = src;
    }
}

// ---------------- shared GEMM machinery ----------------
#define PITCH_B 272
#define A_SZ    (64 * PITCH_B)             // 17408
#define B_SZ    (128 * PITCH_B)            // 34816
#define SMEM_BYTES (2 * A_SZ + 2 * B_SZ)   // 104448

__device__ __forceinline__ void ldsm_x4(uint32_t* r, uint32_t addr) {
    asm volatile("ldmatrix.sync.aligned.m8n8.x4.shared.b16 {%0,%1,%2,%3}, [%4];"
                 : "=r"(r[0]), "=r"(r[1]), "=r"(r[2]), "=r"(r[3]) : "r"(addr));
}
__device__ __forceinline__ void mma16816(float* d, const uint32_t* a, const uint32_t* b) {
    asm volatile(
        "mma.sync.aligned.m16n8k16.row.col.f32.bf16.bf16.f32 "
        "{%0,%1,%2,%3}, {%4,%5,%6,%7}, {%8,%9}, {%0,%1,%2,%3};"
        : "+f"(d[0]), "+f"(d[1]), "+f"(d[2]), "+f"(d[3])
        : "r"(a[0]), "r"(a[1]), "r"(a[2]), "r"(a[3]), "r"(b[0]), "r"(b[1]));
}
__device__ __forceinline__ void sts128u(uint32_t addr, uint4 v) {
    asm volatile("st.shared.v4.b32 [%0], {%1,%2,%3,%4};"
                 :: "r"(addr), "r"(v.x), "r"(v.y), "r"(v.z), "r"(v.w) : "memory");
}

// B-prologue + mainloop + epilogue shared by both GEMM kernels
__device__ __forceinline__ void gemm_body(
    uint32_t sA, uint32_t sB, const float* __restrict__ W,
    const float* __restrict__ bias, bool isRoot, int row0,
    int tid, int wid, int lane, float* __restrict__ Out)
{
    // ---- B: full W 128 x 128, convert ----
#pragma unroll
    for (int i = 0; i < 8; i++) {
        int g = tid + i * 256;                 // 0..2047
        int row = g >> 4;                      // 0..127
        int e0 = (g & 15) * 8;
        float4 w0 = *(const float4*)(W + (size_t)row * DIM + e0);
        float4 w1 = *(const float4*)(W + (size_t)row * DIM + e0 + 4);
        uint4 whi, wlo; cvt8(w0, w1, whi, wlo);
        uint32_t off = (uint32_t)(row * PITCH_B + e0 * 2);
        sts128u(sB + off, whi);
        sts128u(sB + B_SZ + off, wlo);
    }
    __syncthreads();

    const int wm = wid >> 2;
    const int wn = wid & 3;
    const int t4 = lane >> 2;
    const int t2 = (lane & 3) * 2;

    float d[2][4][4];
#pragma unroll
    for (int i = 0; i < 2; i++)
#pragma unroll
        for (int j = 0; j < 4; j++)
#pragma unroll
            for (int q = 0; q < 4; q++) d[i][j][q] = 0.f;

    const uint32_t aRowOff = (uint32_t)((lane & 15) * PITCH_B + (lane >> 4) * 16);
    const uint32_t bRowOff = (uint32_t)((wn * 32 + (lane & 7) + (lane >> 4) * 8) * PITCH_B
                                        + ((lane >> 3) & 1) * 16);

    const int paA[3] = {0, 1, 0};
    const int paB[3] = {0, 0, 1};
#pragma unroll
    for (int p = 0; p < 3; p++) {
        const uint32_t Ab = sA + paA[p] * A_SZ;
        const uint32_t Bb = sB + paB[p] * B_SZ;
#pragma unroll
        for (int ks = 0; ks < 8; ks++) {
            uint32_t a[2][4];
#pragma unroll
            for (int i = 0; i < 2; i++)
                ldsm_x4(a[i], Ab + (uint32_t)((wm * 32 + i * 16) * PITCH_B + ks * 32) + aRowOff);
            uint32_t bf[4][2];
#pragma unroll
            for (int jp = 0; jp < 2; jp++) {
                uint32_t r[4];
                ldsm_x4(r, Bb + (uint32_t)(jp * 16 * PITCH_B + ks * 32) + bRowOff);
                bf[jp * 2 + 0][0] = r[0]; bf[jp * 2 + 0][1] = r[1];
                bf[jp * 2 + 1][0] = r[2]; bf[jp * 2 + 1][1] = r[3];
            }
#pragma unroll
            for (int i = 0; i < 2; i++)
#pragma unroll
                for (int j = 0; j < 4; j++)
                    mma16816(d[i][j], a[i], bf[j]);
        }
    }

#pragma unroll
    for (int i = 0; i < 2; i++) {
#pragma unroll
        for (int half = 0; half < 2; half++) {
            int grow = row0 + wm * 32 + i * 16 + t4 + half * 8;
            if (grow >= N_NODES) continue;
#pragma unroll
            for (int j = 0; j < 4; j++) {
                int col = wn * 32 + j * 8 + t2;
                float2 v = make_float2(d[i][j][half * 2], d[i][j][half * 2 + 1]);
                if (isRoot) { v.x += bias[col]; v.y += bias[col + 1]; }
                *(float2*)(Out + (size_t)grow * DIM + col) = v;
            }
        }
    }
}

// layer 1: A = fp32 x rows, convert in prologue (R5-proven)
__global__ __launch_bounds__(256, 2) void gemm_cvt(
    const float* __restrict__ Xin,
    const float* __restrict__ Wrel, const float* __restrict__ Wroot,
    const float* __restrict__ bias)
{
    extern __shared__ char smem[];
    const uint32_t sA = smem_u32(smem);
    const uint32_t sB = sA + 2 * A_SZ;
    const int tid = threadIdx.x;
    const int wid = tid >> 5;
    const int lane = tid & 31;
    const int row0 = blockIdx.x * 64;
    const bool isRoot = (blockIdx.y == 1);

#pragma unroll
    for (int i = 0; i < 4; i++) {
        int g = tid + i * 256;
        int row = g >> 4;                  // 0..63
        int e0 = (g & 15) * 8;
        int grow = row0 + row;
        float4 v0 = make_float4(0.f, 0.f, 0.f, 0.f), v1 = v0;
        if (grow < N_NODES) {
            v0 = *(const float4*)(Xin + (size_t)grow * DIM + e0);
            v1 = *(const float4*)(Xin + (size_t)grow * DIM + e0 + 4);
        }
        uint4 hi, lo; cvt8(v0, v1, hi, lo);
        uint32_t off = (uint32_t)(row * PITCH_B + e0 * 2);
        sts128u(sA + off, hi);
        sts128u(sA + A_SZ + off, lo);
    }
    gemm_body(sA, sB, isRoot ? Wroot : Wrel, bias, isRoot, row0,
              tid, wid, lane, isRoot ? g_r : g_m);
}

// layer 2: A = preconverted bf16 hi/lo (pure copy)
__global__ __launch_bounds__(256, 2) void gemm_pre(
    const float* __restrict__ Wrel, const float* __restrict__ Wroot,
    const float* __restrict__ bias)
{
    extern __shared__ char smem[];
    const uint32_t sA = smem_u32(smem);
    const uint32_t sB = sA + 2 * A_SZ;
    const int tid = threadIdx.x;
    const int wid = tid >> 5;
    const int lane = tid & 31;
    const int row0 = blockIdx.x * 64;
    const bool isRoot = (blockIdx.y == 1);

#pragma unroll
    for (int i = 0; i < 4; i++) {
        int g = tid + i * 256;             // 0..1023
        int row = g >> 4;
        int v = g & 15;
        size_t srco = (size_t)(row0 + row) * DIM + v * 8;
        uint32_t off = (uint32_t)(row * PITCH_B + v * 16);
        sts128u(sA + off,        *(const uint4*)(g_ahi + srco));
        sts128u(sA + A_SZ + off, *(const uint4*)(g_alo + srco));
    }
    gemm_body(sA, sB, isRoot ? Wroot : Wrel, bias, isRoot, row0,
              tid, wid, lane, isRoot ? g_r : g_m);
}

// ---------------- agg1: h1 = relu(root + sum msgs) -> bf16 hi/lo for gemm2 ----------------
__global__ __launch_bounds__(256) void agg1_kernel() {
    int node = (blockIdx.x * blockDim.x + threadIdx.x) >> 5;
    if (node >= N_NODES) return;
    const int lane = threadIdx.x & 31;
    const float4* __restrict__ M = (const float4*)g_m;
    int s = g_rowptr[node], e = g_rowptr[node + 1];
    float4 acc = make_float4(0.f, 0.f, 0.f, 0.f);
    for (int j = s; j < e; j++) {
        int src = g_srcs[j];
        float4 v = M[(size_t)src * 32 + lane];
        acc.x += v.x; acc.y += v.y; acc.z += v.z; acc.w += v.w;
    }
    float4 r = ((const float4*)g_r)[(size_t)node * 32 + lane];
    r.x = fmaxf(r.x + acc.x, 0.f); r.y = fmaxf(r.y + acc.y, 0.f);
    r.z = fmaxf(r.z + acc.z, 0.f); r.w = fmaxf(r.w + acc.w, 0.f);
    uint2 hi, lo; split4(r, hi, lo);
    ((uint2*)g_ahi)[(size_t)node * 32 + lane] = hi;
    ((uint2*)g_alo)[(size_t)node * 32 + lane] = lo;
}

// ---------------- layer-2 aggregate fused with mean-pool + head ----------------
__global__ __launch_bounds__(256) void agg2_pool_kernel(const void* __restrict__ batch,
                                                        const float* __restrict__ Wout,
                                                        float* __restrict__ out) {
    int node = (blockIdx.x * blockDim.x + threadIdx.x) >> 5;
    if (node >= N_NODES) return;
    const int lane = threadIdx.x & 31;
    const float4* __restrict__ M = (const float4*)g_m;
    int s = g_rowptr[node], e = g_rowptr[node + 1];
    float4 acc = make_float4(0.f, 0.f, 0.f, 0.f);
    for (int j = s; j < e; j++) {
        int src = g_srcs[j];
        float4 v = M[(size_t)src * 32 + lane];
        acc.x += v.x; acc.y += v.y; acc.z += v.z; acc.w += v.w;
    }
    float4 r = ((const float4*)g_r)[(size_t)node * 32 + lane];
    r.x = fmaxf(r.x + acc.x, 0.f); r.y = fmaxf(r.y + acc.y, 0.f);
    r.z = fmaxf(r.z + acc.z, 0.f); r.w = fmaxf(r.w + acc.w, 0.f);
    float4 w = ((const float4*)Wout)[lane];
    float sdot = r.x * w.x + r.y * w.y + r.z * w.z + r.w * w.w;
#pragma unroll
    for (int o = 16; o; o >>= 1) sdot += __shfl_xor_sync(0xffffffffu, sdot, o);
    if (lane == 0) {
        int gidx = ld_idx(batch, node, g_is64);
        int c = g_cnt[gidx]; if (c < 1) c = 1;
        atomicAdd(&out[gidx], sdot / (float)c);
    }
}

// ---------------- launcher (single stream, 10 launches) ----------------
extern "C" void kernel_launch(void* const* d_in, const int* in_sizes, int n_in,
                              void* d_out, int out_size) {
    const float* x       = (const float*)d_in[0];
    const void*  edges   = d_in[1];
    const void*  batch   = d_in[2];
    const float* W1_rel  = (const float*)d_in[3];
    const float* W1_root = (const float*)d_in[4];
    const float* b1      = (const float*)d_in[5];
    const float* W2_rel  = (const float*)d_in[6];
    const float* W2_root = (const float*)d_in[7];
    const float* b2      = (const float*)d_in[8];
    const float* W_out   = (const float*)d_in[9];
    const float* b_out   = (const float*)d_in[10];
    float* out = (float*)d_out;

    cudaFuncSetAttribute(gemm_cvt, cudaFuncAttributeMaxDynamicSharedMemorySize, SMEM_BYTES);
    cudaFuncSetAttribute(gemm_pre, cudaFuncAttributeMaxDynamicSharedMemorySize, SMEM_BYTES);

    const dim3 gemmGrid(PAD_NODES / 64, 2);          // (782, 2)
    const int aggBlks = (N_NODES * 32 + 255) / 256;  // warp per node

    init_kernel<<<(SCAN_N + 255) / 256, 256>>>((const unsigned*)edges, out, b_out);
    hist_count_kernel<<<(N_EDGES + 255) / 256, 256>>>(edges, batch);
    scan1_kernel<<<SCAN_BLKS, 1024>>>();
    scan2_kernel<<<1, 32>>>();
    scan3_kernel<<<SCAN_BLKS, 1024>>>();
    fill_kernel<<<(N_EDGES + 255) / 256, 256>>>(edges);

    gemm_cvt<<<gemmGrid, 256, SMEM_BYTES>>>(x, W1_rel, W1_root, b1);
    agg1_kernel<<<aggBlks, 256>>>();

    gemm_pre<<<gemmGrid, 256, SMEM_BYTES>>>(W2_rel, W2_root, b2);
    agg2_pool_kernel<<<aggBlks, 256>>>(batch, W_out, out);
}

// round 10
// speedup vs baseline: 1.8830x; 1.0186x over previous
#include <cuda_runtime.h>
#include <cuda_bf16.h>
#include <cstdint>

#define N_NODES   50000
#define PAD_NODES 50048          // 782 * 64
#define N_EDGES   500000
#define DIM       128
#define N_GRAPHS  256
#define SCAN_N    (N_NODES + 1)
#define SCAN_BLKS 49             // ceil(50001/1024)

// ---------------- scratch (device globals: allocation-free, zero-init) ----------------
__device__ __align__(16) float g_m[N_NODES * DIM];   // messages  h @ W_rel^T
__device__ __align__(16) float g_r[N_NODES * DIM];   // root + bias (per layer, reused)
__device__ __align__(16) __nv_bfloat16 g_ahi[PAD_NODES * DIM];  // h1 bf16 hi (pad rows stay 0)
__device__ __align__(16) __nv_bfloat16 g_alo[PAD_NODES * DIM];  // h1 bf16 lo
__device__ int g_cnt[N_GRAPHS];
__device__ int g_is64;
// CSR (by destination)
__device__ int g_rowptr[SCAN_N];
__device__ int g_cursor[N_NODES];
__device__ int g_srcs[N_EDGES];
__device__ int g_bsum[SCAN_BLKS];

// ---------------- helpers ----------------
__device__ __forceinline__ uint32_t smem_u32(const void* p) {
    uint32_t a;
    asm("{ .reg .u64 t; cvta.to.shared.u64 t, %1; cvt.u32.u64 %0, t; }" : "=r"(a) : "l"(p));
    return a;
}
__device__ __forceinline__ int ld_idx(const void* p, long long i, int is64) {
    if (is64) return (int)((const long long*)p)[i];
    return ((const int*)p)[i];
}

// split 4 floats -> bf16 hi/lo packed as 2x uint2
__device__ __forceinline__ void split4(float4 v, uint2& hi, uint2& lo) {
    __nv_bfloat16 hx = __float2bfloat16_rn(v.x), hy = __float2bfloat16_rn(v.y);
    __nv_bfloat16 hz = __float2bfloat16_rn(v.z), hw = __float2bfloat16_rn(v.w);
    __nv_bfloat162 h0; h0.x = hx; h0.y = hy;
    __nv_bfloat162 h1; h1.x = hz; h1.y = hw;
    __nv_bfloat162 l0 = __floats2bfloat162_rn(v.x - __bfloat162float(hx),
                                              v.y - __bfloat162float(hy));
    __nv_bfloat162 l1 = __floats2bfloat162_rn(v.z - __bfloat162float(hz),
                                              v.w - __bfloat162float(hw));
    hi.x = *reinterpret_cast<uint32_t*>(&h0); hi.y = *reinterpret_cast<uint32_t*>(&h1);
    lo.x = *reinterpret_cast<uint32_t*>(&l0); lo.y = *reinterpret_cast<uint32_t*>(&l1);
}
__device__ __forceinline__ void cvt8(float4 v0, float4 v1, uint4& hi, uint4& lo) {
    uint2 h0, l0, h1, l1;
    split4(v0, h0, l0);
    split4(v1, h1, l1);
    hi = make_uint4(h0.x, h0.y, h1.x, h1.y);
    lo = make_uint4(l0.x, l0.y, l1.x, l1.y);
}

// ---------------- init: detect + zero rowptr + cnt/out ----------------
__global__ void init_kernel(const unsigned* __restrict__ ew,
                            float* __restrict__ out, const float* __restrict__ b_out) {
    int i = blockIdx.x * blockDim.x + threadIdx.x;
    if (i == 0) {
        unsigned o = 0;
#pragma unroll
        for (int k = 1; k < 64; k += 2) o |= ew[k];
        g_is64 = (o == 0) ? 1 : 0;
    }
    if (i < SCAN_N) g_rowptr[i] = 0;
    if (i < N_GRAPHS) { g_cnt[i] = 0; out[i] = b_out[0]; }
}
__global__ void hist_count_kernel(const void* __restrict__ edges, const void* __restrict__ batch) {
    int e = blockIdx.x * blockDim.x + threadIdx.x;
    int is64 = g_is64;
    if (e < N_EDGES) {
        int dst = ld_idx(edges, (long long)N_EDGES + e, is64);
        atomicAdd(&g_rowptr[dst + 1], 1);
    }
    if (e < N_NODES) atomicAdd(&g_cnt[ld_idx(batch, e, is64)], 1);
}
// ---------------- scan: per-block inclusive (scan1) + apply block offsets (scan3) ----------------
__global__ __launch_bounds__(1024) void scan1_kernel() {
    __shared__ int sd[1024];
    int gid = blockIdx.x * 1024 + threadIdx.x;
    int v = (gid < SCAN_N) ? g_rowptr[gid] : 0;
    sd[threadIdx.x] = v;
    __syncthreads();
#pragma unroll
    for (int off = 1; off < 1024; off <<= 1) {
        int t = (threadIdx.x >= off) ? sd[threadIdx.x - off] : 0;
        __syncthreads();
        sd[threadIdx.x] += t;
        __syncthreads();
    }
    if (gid < SCAN_N) g_rowptr[gid] = sd[threadIdx.x];
    if (threadIdx.x == 1023) g_bsum[blockIdx.x] = sd[1023];
}
// scan3: each block warp-sums its exclusive bsum prefix, applies, seeds cursors
__global__ __launch_bounds__(1024) void scan3_kernel() {
    __shared__ int boff_s;
    if (threadIdx.x < 32) {
        int s = 0;
        for (int i = threadIdx.x; i < (int)blockIdx.x; i += 32) s += g_bsum[i];
#pragma unroll
        for (int o = 16; o; o >>= 1) s += __shfl_xor_sync(0xffffffffu, s, o);
        if (threadIdx.x == 0) boff_s = s;
    }
    __syncthreads();
    const int boff = boff_s;
    int gid = blockIdx.x * 1024 + threadIdx.x;
    if (gid < SCAN_N) {
        int v = g_rowptr[gid] + boff;
        g_rowptr[gid] = v;
        if (gid < N_NODES) g_cursor[gid] = v;   // seed fill cursor with row start
    }
}
__global__ void fill_kernel(const void* __restrict__ edges) {
    int e = blockIdx.x * blockDim.x + threadIdx.x;
    if (e < N_EDGES) {
        int is64 = g_is64;
        int src = ld_idx(edges, e, is64);
        int dst = ld_idx(edges, (long long)N_EDGES + e, is64);
        int pos = atomicAdd(&g_cursor[dst], 1);
        g_srcs[pos] = src;
    }
}

// ---------------- shared GEMM machinery ----------------
#define PITCH_B 272
#define A_SZ    (64 * PITCH_B)             // 17408
#define B_SZ    (128 * PITCH_B)            // 34816
#define SMEM_BYTES (2 * A_SZ + 2 * B_SZ)   // 104448

__device__ __forceinline__ void ldsm_x4(uint32_t* r, uint32_t addr) {
    asm volatile("ldmatrix.sync.aligned.m8n8.x4.shared.b16 {%0,%1,%2,%3}, [%4];"
                 : "=r"(r[0]), "=r"(r[1]), "=r"(r[2]), "=r"(r[3]) : "r"(addr));
}
__device__ __forceinline__ void mma16816(float* d, const uint32_t* a, const uint32_t* b) {
    asm volatile(
        "mma.sync.aligned.m16n8k16.row.col.f32.bf16.bf16.f32 "
        "{%0,%1,%2,%3}, {%4,%5,%6,%7}, {%8,%9}, {%0,%1,%2,%3};"
        : "+f"(d[0]), "+f"(d[1]), "+f"(d[2]), "+f"(d[3])
        : "r"(a[0]), "r"(a[1]), "r"(a[2]), "r"(a[3]), "r"(b[0]), "r"(b[1]));
}
__device__ __forceinline__ void sts128u(uint32_t addr, uint4 v) {
    asm volatile("st.shared.v4.b32 [%0], {%1,%2,%3,%4};"
                 :: "r"(addr), "r"(v.x), "r"(v.y), "r"(v.z), "r"(v.w) : "memory");
}

// B-prologue + mainloop + epilogue shared by both GEMM kernels
__device__ __forceinline__ void gemm_body(
    uint32_t sA, uint32_t sB, const float* __restrict__ W,
    const float* __restrict__ bias, bool isRoot, int row0,
    int tid, int wid, int lane, float* __restrict__ Out)
{
    // ---- B: full W 128 x 128, convert ----
#pragma unroll
    for (int i = 0; i < 8; i++) {
        int g = tid + i * 256;                 // 0..2047
        int row = g >> 4;                      // 0..127
        int e0 = (g & 15) * 8;
        float4 w0 = *(const float4*)(W + (size_t)row * DIM + e0);
        float4 w1 = *(const float4*)(W + (size_t)row * DIM + e0 + 4);
        uint4 whi, wlo; cvt8(w0, w1, whi, wlo);
        uint32_t off = (uint32_t)(row * PITCH_B + e0 * 2);
        sts128u(sB + off, whi);
        sts128u(sB + B_SZ + off, wlo);
    }
    __syncthreads();

    const int wm = wid >> 2;
    const int wn = wid & 3;
    const int t4 = lane >> 2;
    const int t2 = (lane & 3) * 2;

    float d[2][4][4];
#pragma unroll
    for (int i = 0; i < 2; i++)
#pragma unroll
        for (int j = 0; j < 4; j++)
#pragma unroll
            for (int q = 0; q < 4; q++) d[i][j][q] = 0.f;

    const uint32_t aRowOff = (uint32_t)((lane & 15) * PITCH_B + (lane >> 4) * 16);
    const uint32_t bRowOff = (uint32_t)((wn * 32 + (lane & 7) + (lane >> 4) * 8) * PITCH_B
                                        + ((lane >> 3) & 1) * 16);

    const int paA[3] = {0, 1, 0};
    const int paB[3] = {0, 0, 1};
#pragma unroll
    for (int p = 0; p < 3; p++) {
        const uint32_t Ab = sA + paA[p] * A_SZ;
        const uint32_t Bb = sB + paB[p] * B_SZ;
#pragma unroll
        for (int ks = 0; ks < 8; ks++) {
            uint32_t a[2][4];
#pragma unroll
            for (int i = 0; i < 2; i++)
                ldsm_x4(a[i], Ab + (uint32_t)((wm * 32 + i * 16) * PITCH_B + ks * 32) + aRowOff);
            uint32_t bf[4][2];
#pragma unroll
            for (int jp = 0; jp < 2; jp++) {
                uint32_t r[4];
                ldsm_x4(r, Bb + (uint32_t)(jp * 16 * PITCH_B + ks * 32) + bRowOff);
                bf[jp * 2 + 0][0] = r[0]; bf[jp * 2 + 0][1] = r[1];
                bf[jp * 2 + 1][0] = r[2]; bf[jp * 2 + 1][1] = r[3];
            }
#pragma unroll
            for (int i = 0; i < 2; i++)
#pragma unroll
                for (int j = 0; j < 4; j++)
                    mma16816(d[i][j], a[i], bf[j]);
        }
    }

#pragma unroll
    for (int i = 0; i < 2; i++) {
#pragma unroll
        for (int half = 0; half < 2; half++) {
            int grow = row0 + wm * 32 + i * 16 + t4 + half * 8;
            if (grow >= N_NODES) continue;
#pragma unroll
            for (int j = 0; j < 4; j++) {
                int col = wn * 32 + j * 8 + t2;
                float2 v = make_float2(d[i][j][half * 2], d[i][j][half * 2 + 1]);
                if (isRoot) { v.x += bias[col]; v.y += bias[col + 1]; }
                *(float2*)(Out + (size_t)grow * DIM + col) = v;
            }
        }
    }
}

// layer 1: A = fp32 x rows, convert in prologue (R5-proven)
__global__ __launch_bounds__(256, 2) void gemm_cvt(
    const float* __restrict__ Xin,
    const float* __restrict__ Wrel, const float* __restrict__ Wroot,
    const float* __restrict__ bias)
{
    extern __shared__ char smem[];
    const uint32_t sA = smem_u32(smem);
    const uint32_t sB = sA + 2 * A_SZ;
    const int tid = threadIdx.x;
    const int wid = tid >> 5;
    const int lane = tid & 31;
    const int row0 = blockIdx.x * 64;
    const bool isRoot = (blockIdx.y == 1);

#pragma unroll
    for (int i = 0; i < 4; i++) {
        int g = tid + i * 256;
        int row = g >> 4;                  // 0..63
        int e0 = (g & 15) * 8;
        int grow = row0 + row;
        float4 v0 = make_float4(0.f, 0.f, 0.f, 0.f), v1 = v0;
        if (grow < N_NODES) {
            v0 = *(const float4*)(Xin + (size_t)grow * DIM + e0);
            v1 = *(const float4*)(Xin + (size_t)grow * DIM + e0 + 4);
        }
        uint4 hi, lo; cvt8(v0, v1, hi, lo);
        uint32_t off = (uint32_t)(row * PITCH_B + e0 * 2);
        sts128u(sA + off, hi);
        sts128u(sA + A_SZ + off, lo);
    }
    gemm_body(sA, sB, isRoot ? Wroot : Wrel, bias, isRoot, row0,
              tid, wid, lane, isRoot ? g_r : g_m);
}

// layer 2: A = preconverted bf16 hi/lo (pure copy)
__global__ __launch_bounds__(256, 2) void gemm_pre(
    const float* __restrict__ Wrel, const float* __restrict__ Wroot,
    const float* __restrict__ bias)
{
    extern __shared__ char smem[];
    const uint32_t sA = smem_u32(smem);
    const uint32_t sB = sA + 2 * A_SZ;
    const int tid = threadIdx.x;
    const int wid = tid >> 5;
    const int lane = tid & 31;
    const int row0 = blockIdx.x * 64;
    const bool isRoot = (blockIdx.y == 1);

#pragma unroll
    for (int i = 0; i < 4; i++) {
        int g = tid + i * 256;             // 0..1023
        int row = g >> 4;
        int v = g & 15;
        size_t srco = (size_t)(row0 + row) * DIM + v * 8;
        uint32_t off = (uint32_t)(row * PITCH_B + v * 16);
        sts128u(sA + off,        *(const uint4*)(g_ahi + srco));
        sts128u(sA + A_SZ + off, *(const uint4*)(g_alo + srco));
    }
    gemm_body(sA, sB, isRoot ? Wroot : Wrel, bias, isRoot, row0,
              tid, wid, lane, isRoot ? g_r : g_m);
}

// ---------------- agg1: h1 = relu(root + sum msgs) -> bf16 hi/lo for gemm2 ----------------
__global__ __launch_bounds__(256) void agg1_kernel() {
    int node = (blockIdx.x * blockDim.x + threadIdx.x) >> 5;
    if (node >= N_NODES) return;
    const int lane = threadIdx.x & 31;
    const float4* __restrict__ M = (const float4*)g_m;
    int s = g_rowptr[node], e = g_rowptr[node + 1];
    float4 acc = make_float4(0.f, 0.f, 0.f, 0.f);
    for (int j = s; j < e; j++) {
        int src = g_srcs[j];
        float4 v = M[(size_t)src * 32 + lane];
        acc.x += v.x; acc.y += v.y; acc.z += v.z; acc.w += v.w;
    }
    float4 r = ((const float4*)g_r)[(size_t)node * 32 + lane];
    r.x = fmaxf(r.x + acc.x, 0.f); r.y = fmaxf(r.y + acc.y, 0.f);
    r.z = fmaxf(r.z + acc.z, 0.f); r.w = fmaxf(r.w + acc.w, 0.f);
    uint2 hi, lo; split4(r, hi, lo);
    ((uint2*)g_ahi)[(size_t)node * 32 + lane] = hi;
    ((uint2*)g_alo)[(size_t)node * 32 + lane] = lo;
}

// ---------------- layer-2 aggregate fused with mean-pool + head ----------------
__global__ __launch_bounds__(256) void agg2_pool_kernel(const void* __restrict__ batch,
                                                        const float* __restrict__ Wout,
                                                        float* __restrict__ out) {
    int node = (blockIdx.x * blockDim.x + threadIdx.x) >> 5;
    if (node >= N_NODES) return;
    const int lane = threadIdx.x & 31;
    const float4* __restrict__ M = (const float4*)g_m;
    int s = g_rowptr[node], e = g_rowptr[node + 1];
    float4 acc = make_float4(0.f, 0.f, 0.f, 0.f);
    for (int j = s; j < e; j++) {
        int src = g_srcs[j];
        float4 v = M[(size_t)src * 32 + lane];
        acc.x += v.x; acc.y += v.y; acc.z += v.z; acc.w += v.w;
    }
    float4 r = ((const float4*)g_r)[(size_t)node * 32 + lane];
    r.x = fmaxf(r.x + acc.x, 0.f); r.y = fmaxf(r.y + acc.y, 0.f);
    r.z = fmaxf(r.z + acc.z, 0.f); r.w = fmaxf(r.w + acc.w, 0.f);
    float4 w = ((const float4*)Wout)[lane];
    float sdot = r.x * w.x + r.y * w.y + r.z * w.z + r.w * w.w;
#pragma unroll
    for (int o = 16; o; o >>= 1) sdot += __shfl_xor_sync(0xffffffffu, sdot, o);
    if (lane == 0) {
        int gidx = ld_idx(batch, node, g_is64);
        int c = g_cnt[gidx]; if (c < 1) c = 1;
        atomicAdd(&out[gidx], sdot / (float)c);
    }
}

// ---------------- launcher (single stream, 9 launches; gemm_cvt 4th for ncu) ----------------
extern "C" void kernel_launch(void* const* d_in, const int* in_sizes, int n_in,
                              void* d_out, int out_size) {
    const float* x       = (const float*)d_in[0];
    const void*  edges   = d_in[1];
    const void*  batch   = d_in[2];
    const float* W1_rel  = (const float*)d_in[3];
    const float* W1_root = (const float*)d_in[4];
    const float* b1      = (const float*)d_in[5];
    const float* W2_rel  = (const float*)d_in[6];
    const float* W2_root = (const float*)d_in[7];
    const float* b2      = (const float*)d_in[8];
    const float* W_out   = (const float*)d_in[9];
    const float* b_out   = (const float*)d_in[10];
    float* out = (float*)d_out;

    cudaFuncSetAttribute(gemm_cvt, cudaFuncAttributeMaxDynamicSharedMemorySize, SMEM_BYTES);
    cudaFuncSetAttribute(gemm_pre, cudaFuncAttributeMaxDynamicSharedMemorySize, SMEM_BYTES);

    const dim3 gemmGrid(PAD_NODES / 64, 2);          // (782, 2)
    const int aggBlks = (N_NODES * 32 + 255) / 256;  // warp per node

    init_kernel<<<(SCAN_N + 255) / 256, 256>>>((const unsigned*)edges, out, b_out);
    hist_count_kernel<<<(N_EDGES + 255) / 256, 256>>>(edges, batch);
    scan1_kernel<<<SCAN_BLKS, 1024>>>();
    // gemm_cvt is independent of the CSR chain; placed 4th so ncu profiles it
    gemm_cvt<<<gemmGrid, 256, SMEM_BYTES>>>(x, W1_rel, W1_root, b1);
    scan3_kernel<<<SCAN_BLKS, 1024>>>();
    fill_kernel<<<(N_EDGES + 255) / 256, 256>>>(edges);

    agg1_kernel<<<aggBlks, 256>>>();

    gemm_pre<<<gemmGrid, 256, SMEM_BYTES>>>(W2_rel, W2_root, b2);
    agg2_pool_kernel<<<aggBlks, 256>>>(batch, W_out, out);
}

// round 11
// speedup vs baseline: 2.1094x; 1.1202x over previous
#include <cuda_runtime.h>
#include <cuda_bf16.h>
#include <cstdint>

#define N_NODES   50000
#define PAD_NODES 50048          // 391 * 128
#define N_EDGES   500000
#define DIM       128
#define N_GRAPHS  256
#define SCAN_N    (N_NODES + 1)
#define SCAN_BLKS 49             // ceil(50001/1024)

// ---------------- scratch (device globals: allocation-free, zero-init) ----------------
__device__ __align__(16) float g_m[N_NODES * DIM];   // messages  h @ W_rel^T
__device__ __align__(16) float g_r[N_NODES * DIM];   // root + bias (per layer, reused)
__device__ __align__(16) __nv_bfloat16 g_ahi[PAD_NODES * DIM];  // h1 bf16 hi (pad rows stay 0)
__device__ __align__(16) __nv_bfloat16 g_alo[PAD_NODES * DIM];  // h1 bf16 lo
__device__ __align__(16) __nv_bfloat16 g_whi[2][256 * DIM];     // W hi: rows 0-127 rel, 128-255 root
__device__ __align__(16) __nv_bfloat16 g_wlo[2][256 * DIM];     // W lo
__device__ int g_cnt[N_GRAPHS];
__device__ int g_is64;
// CSR (by destination)
__device__ int g_rowptr[SCAN_N];
__device__ int g_cursor[N_NODES];
__device__ int g_srcs[N_EDGES];
__device__ int g_bsum[SCAN_BLKS];

// ---------------- helpers ----------------
__device__ __forceinline__ uint32_t smem_u32(const void* p) {
    uint32_t a;
    asm("{ .reg .u64 t; cvta.to.shared.u64 t, %1; cvt.u32.u64 %0, t; }" : "=r"(a) : "l"(p));
    return a;
}
__device__ __forceinline__ int ld_idx(const void* p, long long i, int is64) {
    if (is64) return (int)((const long long*)p)[i];
    return ((const int*)p)[i];
}

// split 4 floats -> bf16 hi/lo packed as 2x uint2
__device__ __forceinline__ void split4(float4 v, uint2& hi, uint2& lo) {
    __nv_bfloat16 hx = __float2bfloat16_rn(v.x), hy = __float2bfloat16_rn(v.y);
    __nv_bfloat16 hz = __float2bfloat16_rn(v.z), hw = __float2bfloat16_rn(v.w);
    __nv_bfloat162 h0; h0.x = hx; h0.y = hy;
    __nv_bfloat162 h1; h1.x = hz; h1.y = hw;
    __nv_bfloat162 l0 = __floats2bfloat162_rn(v.x - __bfloat162float(hx),
                                              v.y - __bfloat162float(hy));
    __nv_bfloat162 l1 = __floats2bfloat162_rn(v.z - __bfloat162float(hz),
                                              v.w - __bfloat162float(hw));
    hi.x = *reinterpret_cast<uint32_t*>(&h0); hi.y = *reinterpret_cast<uint32_t*>(&h1);
    lo.x = *reinterpret_cast<uint32_t*>(&l0); lo.y = *reinterpret_cast<uint32_t*>(&l1);
}
__device__ __forceinline__ void cvt8(float4 v0, float4 v1, uint4& hi, uint4& lo) {
    uint2 h0, l0, h1, l1;
    split4(v0, h0, l0);
    split4(v1, h1, l1);
    hi = make_uint4(h0.x, h0.y, h1.x, h1.y);
    lo = make_uint4(l0.x, l0.y, l1.x, l1.y);
}

// ---------------- init: detect + zero rowptr + cnt/out + W convert ----------------
__global__ void init_kernel(const unsigned* __restrict__ ew,
                            float* __restrict__ out, const float* __restrict__ b_out,
                            const float* __restrict__ W1rel, const float* __restrict__ W1root,
                            const float* __restrict__ W2rel, const float* __restrict__ W2root) {
    int i = blockIdx.x * blockDim.x + threadIdx.x;
    if (i == 0) {
        unsigned o = 0;
#pragma unroll
        for (int k = 1; k < 64; k += 2) o |= ew[k];
        g_is64 = (o == 0) ? 1 : 0;
    }
    if (i < SCAN_N) g_rowptr[i] = 0;
    if (i < N_GRAPHS) { g_cnt[i] = 0; out[i] = b_out[0]; }
    if (i < 4 * 128 * DIM / 4) {                   // 16384 weight-convert threads
        int mat = i / (128 * DIM / 4);             // 0..3
        int off = (i % (128 * DIM / 4)) * 4;
        const float* src = (mat == 0) ? W1rel : (mat == 1) ? W1root
                         : (mat == 2) ? W2rel : W2root;
        int layer = mat >> 1;
        int half = mat & 1;                        // 0 rel -> rows 0-127, 1 root -> 128-255
        float4 v = *(const float4*)(src + off);
        uint2 hi, lo; split4(v, hi, lo);
        size_t dsto = (size_t)half * 128 * DIM + off;
        *(uint2*)(&g_whi[layer][dsto]) = hi;
        *(uint2*)(&g_wlo[layer][dsto]) = lo;
    }
}
__global__ void hist_count_kernel(const void* __restrict__ edges, const void* __restrict__ batch) {
    int e = blockIdx.x * blockDim.x + threadIdx.x;
    int is64 = g_is64;
    if (e < N_EDGES) {
        int dst = ld_idx(edges, (long long)N_EDGES + e, is64);
        atomicAdd(&g_rowptr[dst + 1], 1);
    }
    if (e < N_NODES) atomicAdd(&g_cnt[ld_idx(batch, e, is64)], 1);
}
// ---------------- scan: per-block inclusive (scan1) + apply block offsets (scan3) ----------------
__global__ __launch_bounds__(1024) void scan1_kernel() {
    __shared__ int sd[1024];
    int gid = blockIdx.x * 1024 + threadIdx.x;
    int v = (gid < SCAN_N) ? g_rowptr[gid] : 0;
    sd[threadIdx.x] = v;
    __syncthreads();
#pragma unroll
    for (int off = 1; off < 1024; off <<= 1) {
        int t = (threadIdx.x >= off) ? sd[threadIdx.x - off] : 0;
        __syncthreads();
        sd[threadIdx.x] += t;
        __syncthreads();
    }
    if (gid < SCAN_N) g_rowptr[gid] = sd[threadIdx.x];
    if (threadIdx.x == 1023) g_bsum[blockIdx.x] = sd[1023];
}
// scan3: each block warp-sums its exclusive bsum prefix, applies, seeds cursors
__global__ __launch_bounds__(1024) void scan3_kernel() {
    __shared__ int boff_s;
    if (threadIdx.x < 32) {
        int s = 0;
        for (int i = threadIdx.x; i < (int)blockIdx.x; i += 32) s += g_bsum[i];
#pragma unroll
        for (int o = 16; o; o >>= 1) s += __shfl_xor_sync(0xffffffffu, s, o);
        if (threadIdx.x == 0) boff_s = s;
    }
    __syncthreads();
    const int boff = boff_s;
    int gid = blockIdx.x * 1024 + threadIdx.x;
    if (gid < SCAN_N) {
        int v = g_rowptr[gid] + boff;
        g_rowptr[gid] = v;
        if (gid < N_NODES) g_cursor[gid] = v;   // seed fill cursor with row start
    }
}
__global__ void fill_kernel(const void* __restrict__ edges) {
    int e = blockIdx.x * blockDim.x + threadIdx.x;
    if (e < N_EDGES) {
        int is64 = g_is64;
        int src = ld_idx(edges, e, is64);
        int dst = ld_idx(edges, (long long)N_EDGES + e, is64);
        int pos = atomicAdd(&g_cursor[dst], 1);
        g_srcs[pos] = src;
    }
}

// ---------------- GEMM: 128x128 tile, 512 threads (4x4 warps, 32x32 warp tile) ----------------
#define PITCH_B 272
#define A_SZ    (128 * PITCH_B)            // 34816
#define B_SZ    (128 * PITCH_B)            // 34816
#define SMEM_BYTES (2 * A_SZ + 2 * B_SZ)   // 139264

__device__ __forceinline__ void ldsm_x4(uint32_t* r, uint32_t addr) {
    asm volatile("ldmatrix.sync.aligned.m8n8.x4.shared.b16 {%0,%1,%2,%3}, [%4];"
                 : "=r"(r[0]), "=r"(r[1]), "=r"(r[2]), "=r"(r[3]) : "r"(addr));
}
__device__ __forceinline__ void mma16816(float* d, const uint32_t* a, const uint32_t* b) {
    asm volatile(
        "mma.sync.aligned.m16n8k16.row.col.f32.bf16.bf16.f32 "
        "{%0,%1,%2,%3}, {%4,%5,%6,%7}, {%8,%9}, {%0,%1,%2,%3};"
        : "+f"(d[0]), "+f"(d[1]), "+f"(d[2]), "+f"(d[3])
        : "r"(a[0]), "r"(a[1]), "r"(a[2]), "r"(a[3]), "r"(b[0]), "r"(b[1]));
}
__device__ __forceinline__ void sts128u(uint32_t addr, uint4 v) {
    asm volatile("st.shared.v4.b32 [%0], {%1,%2,%3,%4};"
                 :: "r"(addr), "r"(v.x), "r"(v.y), "r"(v.z), "r"(v.w) : "memory");
}

// B copy-prologue + fused 3-term mainloop + epilogue (shared by both GEMM kernels)
__device__ __forceinline__ void gemm_body(
    uint32_t sA, uint32_t sB, int layer, bool isRoot,
    const float* __restrict__ bias, int row0,
    int tid, int wid, int lane, float* __restrict__ Out)
{
    // ---- B: 128 rows x 128 bf16 (hi & lo), pure copy ----
    const __nv_bfloat16* __restrict__ Bh = g_whi[layer] + (size_t)(isRoot ? 128 : 0) * DIM;
    const __nv_bfloat16* __restrict__ Bl = g_wlo[layer] + (size_t)(isRoot ? 128 : 0) * DIM;
#pragma unroll
    for (int i = 0; i < 4; i++) {
        int g = tid + i * 512;                 // 0..2047
        int row = g >> 4;                      // 0..127
        int v = g & 15;
        size_t srco = (size_t)row * DIM + v * 8;
        uint32_t off = (uint32_t)(row * PITCH_B + v * 16);
        sts128u(sB + off,        *(const uint4*)(Bh + srco));
        sts128u(sB + B_SZ + off, *(const uint4*)(Bl + srco));
    }
    __syncthreads();

    const int wm = wid >> 2;                   // 0..3
    const int wn = wid & 3;                    // 0..3
    const int t4 = lane >> 2;
    const int t2 = (lane & 3) * 2;

    float d[2][4][4];
#pragma unroll
    for (int i = 0; i < 2; i++)
#pragma unroll
        for (int j = 0; j < 4; j++)
#pragma unroll
            for (int q = 0; q < 4; q++) d[i][j][q] = 0.f;

    const uint32_t aRowOff = (uint32_t)((lane & 15) * PITCH_B + (lane >> 4) * 16);
    const uint32_t bRowOff = (uint32_t)((wn * 32 + (lane & 7) + (lane >> 4) * 8) * PITCH_B
                                        + ((lane >> 3) & 1) * 16);

#pragma unroll
    for (int ks = 0; ks < 8; ks++) {
        // load A hi/lo fragments once
        uint32_t aH[2][4], aL[2][4];
#pragma unroll
        for (int i = 0; i < 2; i++) {
            uint32_t base = (uint32_t)((wm * 32 + i * 16) * PITCH_B + ks * 32) + aRowOff;
            ldsm_x4(aH[i], sA + base);
            ldsm_x4(aL[i], sA + A_SZ + base);
        }
        // load B hi/lo fragments once
        uint32_t bH[4][2], bL[4][2];
#pragma unroll
        for (int jp = 0; jp < 2; jp++) {
            uint32_t base = (uint32_t)(jp * 16 * PITCH_B + ks * 32) + bRowOff;
            uint32_t r[4];
            ldsm_x4(r, sB + base);
            bH[jp * 2 + 0][0] = r[0]; bH[jp * 2 + 0][1] = r[1];
            bH[jp * 2 + 1][0] = r[2]; bH[jp * 2 + 1][1] = r[3];
            ldsm_x4(r, sB + B_SZ + base);
            bL[jp * 2 + 0][0] = r[0]; bL[jp * 2 + 0][1] = r[1];
            bL[jp * 2 + 1][0] = r[2]; bL[jp * 2 + 1][1] = r[3];
        }
        // 3 accumulation terms: hh + lh + hl
#pragma unroll
        for (int i = 0; i < 2; i++)
#pragma unroll
            for (int j = 0; j < 4; j++) {
                mma16816(d[i][j], aH[i], bH[j]);
                mma16816(d[i][j], aL[i], bH[j]);
                mma16816(d[i][j], aH[i], bL[j]);
            }
    }

#pragma unroll
    for (int i = 0; i < 2; i++) {
#pragma unroll
        for (int half = 0; half < 2; half++) {
            int grow = row0 + wm * 32 + i * 16 + t4 + half * 8;
            if (grow >= N_NODES) continue;
#pragma unroll
            for (int j = 0; j < 4; j++) {
                int col = wn * 32 + j * 8 + t2;
                float2 v = make_float2(d[i][j][half * 2], d[i][j][half * 2 + 1]);
                if (isRoot) { v.x += bias[col]; v.y += bias[col + 1]; }
                *(float2*)(Out + (size_t)grow * DIM + col) = v;
            }
        }
    }
}

// layer 1: A = fp32 x rows, convert in prologue
__global__ __launch_bounds__(512, 1) void gemm_cvt(
    const float* __restrict__ Xin, const float* __restrict__ bias)
{
    extern __shared__ char smem[];
    const uint32_t sA = smem_u32(smem);
    const uint32_t sB = sA + 2 * A_SZ;
    const int tid = threadIdx.x;
    const int wid = tid >> 5;
    const int lane = tid & 31;
    const int row0 = blockIdx.x * 128;
    const bool isRoot = (blockIdx.y == 1);

#pragma unroll
    for (int i = 0; i < 4; i++) {
        int g = tid + i * 512;             // 0..2047
        int row = g >> 4;                  // 0..127
        int e0 = (g & 15) * 8;
        int grow = row0 + row;
        float4 v0 = make_float4(0.f, 0.f, 0.f, 0.f), v1 = v0;
        if (grow < N_NODES) {
            v0 = *(const float4*)(Xin + (size_t)grow * DIM + e0);
            v1 = *(const float4*)(Xin + (size_t)grow * DIM + e0 + 4);
        }
        uint4 hi, lo; cvt8(v0, v1, hi, lo);
        uint32_t off = (uint32_t)(row * PITCH_B + e0 * 2);
        sts128u(sA + off, hi);
        sts128u(sA + A_SZ + off, lo);
    }
    gemm_body(sA, sB, 0, isRoot, bias, row0, tid, wid, lane, isRoot ? g_r : g_m);
}

// layer 2: A = preconverted bf16 hi/lo (pure copy)
__global__ __launch_bounds__(512, 1) void gemm_pre(const float* __restrict__ bias)
{
    extern __shared__ char smem[];
    const uint32_t sA = smem_u32(smem);
    const uint32_t sB = sA + 2 * A_SZ;
    const int tid = threadIdx.x;
    const int wid = tid >> 5;
    const int lane = tid & 31;
    const int row0 = blockIdx.x * 128;
    const bool isRoot = (blockIdx.y == 1);

#pragma unroll
    for (int i = 0; i < 4; i++) {
        int g = tid + i * 512;             // 0..2047
        int row = g >> 4;                  // 0..127
        int v = g & 15;
        size_t srco = (size_t)(row0 + row) * DIM + v * 8;
        uint32_t off = (uint32_t)(row * PITCH_B + v * 16);
        sts128u(sA + off,        *(const uint4*)(g_ahi + srco));
        sts128u(sA + A_SZ + off, *(const uint4*)(g_alo + srco));
    }
    gemm_body(sA, sB, 1, isRoot, bias, row0, tid, wid, lane, isRoot ? g_r : g_m);
}

// ---------------- agg1: h1 = relu(root + sum msgs) -> bf16 hi/lo for gemm2 ----------------
__global__ __launch_bounds__(256) void agg1_kernel() {
    int node = (blockIdx.x * blockDim.x + threadIdx.x) >> 5;
    if (node >= N_NODES) return;
    const int lane = threadIdx.x & 31;
    const float4* __restrict__ M = (const float4*)g_m;
    int s = g_rowptr[node], e = g_rowptr[node + 1];
    float4 acc = make_float4(0.f, 0.f, 0.f, 0.f);
    for (int j = s; j < e; j++) {
        int src = g_srcs[j];
        float4 v = M[(size_t)src * 32 + lane];
        acc.x += v.x; acc.y += v.y; acc.z += v.z; acc.w += v.w;
    }
    float4 r = ((const float4*)g_r)[(size_t)node * 32 + lane];
    r.x = fmaxf(r.x + acc.x, 0.f); r.y = fmaxf(r.y + acc.y, 0.f);
    r.z = fmaxf(r.z + acc.z, 0.f); r.w = fmaxf(r.w + acc.w, 0.f);
    uint2 hi, lo; split4(r, hi, lo);
    ((uint2*)g_ahi)[(size_t)node * 32 + lane] = hi;
    ((uint2*)g_alo)[(size_t)node * 32 + lane] = lo;
}

// ---------------- layer-2 aggregate fused with mean-pool + head ----------------
__global__ __launch_bounds__(256) void agg2_pool_kernel(const void* __restrict__ batch,
                                                        const float* __restrict__ Wout,
                                                        float* __restrict__ out) {
    int node = (blockIdx.x * blockDim.x + threadIdx.x) >> 5;
    if (node >= N_NODES) return;
    const int lane = threadIdx.x & 31;
    const float4* __restrict__ M = (const float4*)g_m;
    int s = g_rowptr[node], e = g_rowptr[node + 1];
    float4 acc = make_float4(0.f, 0.f, 0.f, 0.f);
    for (int j = s; j < e; j++) {
        int src = g_srcs[j];
        float4 v = M[(size_t)src * 32 + lane];
        acc.x += v.x; acc.y += v.y; acc.z += v.z; acc.w += v.w;
    }
    float4 r = ((const float4*)g_r)[(size_t)node * 32 + lane];
    r.x = fmaxf(r.x + acc.x, 0.f); r.y = fmaxf(r.y + acc.y, 0.f);
    r.z = fmaxf(r.z + acc.z, 0.f); r.w = fmaxf(r.w + acc.w, 0.f);
    float4 w = ((const float4*)Wout)[lane];
    float sdot = r.x * w.x + r.y * w.y + r.z * w.z + r.w * w.w;
#pragma unroll
    for (int o = 16; o; o >>= 1) sdot += __shfl_xor_sync(0xffffffffu, sdot, o);
    if (lane == 0) {
        int gidx = ld_idx(batch, node, g_is64);
        int c = g_cnt[gidx]; if (c < 1) c = 1;
        atomicAdd(&out[gidx], sdot / (float)c);
    }
}

// ---------------- launcher (single stream, 9 launches; gemm_cvt 4th for ncu) ----------------
extern "C" void kernel_launch(void* const* d_in, const int* in_sizes, int n_in,
                              void* d_out, int out_size) {
    const float* x       = (const float*)d_in[0];
    const void*  edges   = d_in[1];
    const void*  batch   = d_in[2];
    const float* W1_rel  = (const float*)d_in[3];
    const float* W1_root = (const float*)d_in[4];
    const float* b1      = (const float*)d_in[5];
    const float* W2_rel  = (const float*)d_in[6];
    const float* W2_root = (const float*)d_in[7];
    const float* b2      = (const float*)d_in[8];
    const float* W_out   = (const float*)d_in[9];
    const float* b_out   = (const float*)d_in[10];
    float* out = (float*)d_out;

    cudaFuncSetAttribute(gemm_cvt, cudaFuncAttributeMaxDynamicSharedMemorySize, SMEM_BYTES);
    cudaFuncSetAttribute(gemm_pre, cudaFuncAttributeMaxDynamicSharedMemorySize, SMEM_BYTES);

    const dim3 gemmGrid(PAD_NODES / 128, 2);         // (391, 2)
    const int aggBlks = (N_NODES * 32 + 255) / 256;  // warp per node

    init_kernel<<<(SCAN_N + 255) / 256, 256>>>((const unsigned*)edges, out, b_out,
                                               W1_rel, W1_root, W2_rel, W2_root);
    hist_count_kernel<<<(N_EDGES + 255) / 256, 256>>>(edges, batch);
    scan1_kernel<<<SCAN_BLKS, 1024>>>();
    // gemm_cvt is independent of the CSR chain; placed 4th so ncu profiles it
    gemm_cvt<<<gemmGrid, 512, SMEM_BYTES>>>(x, b1);
    scan3_kernel<<<SCAN_BLKS, 1024>>>();
    fill_kernel<<<(N_EDGES + 255) / 256, 256>>>(edges);

    agg1_kernel<<<aggBlks, 256>>>();

    gemm_pre<<<gemmGrid, 512, SMEM_BYTES>>>(b2);
    agg2_pool_kernel<<<aggBlks, 256>>>(batch, W_out, out);
}

// round 15
// speedup vs baseline: 2.1989x; 1.0424x over previous
#include <cuda_runtime.h>
#include <cuda_bf16.h>
#include <cstdint>

#define N_NODES   50000
#define PAD_NODES 50048          // 782 * 64
#define N_EDGES   500000
#define DIM       128
#define N_GRAPHS  256
#define SCAN_N    (N_NODES + 1)
#define SCAN_BLKS 49             // ceil(50001/1024)

// ---------------- scratch (device globals: allocation-free, zero-init) ----------------
__device__ __align__(16) float g_m[N_NODES * DIM];   // messages  h @ W_rel^T
__device__ __align__(16) float g_r[N_NODES * DIM];   // root + bias (per layer, reused)
__device__ __align__(16) __nv_bfloat16 g_ahi[PAD_NODES * DIM];  // h1 bf16 hi (pad rows stay 0)
__device__ __align__(16) __nv_bfloat16 g_alo[PAD_NODES * DIM];  // h1 bf16 lo
__device__ __align__(16) __nv_bfloat16 g_whi[2][256 * DIM];     // W hi: rows 0-127 rel, 128-255 root
__device__ __align__(16) __nv_bfloat16 g_wlo[2][256 * DIM];     // W lo
__device__ int g_cnt[N_GRAPHS];
__device__ int g_is64;
// CSR (by destination)
__device__ int g_rowptr[SCAN_N];
__device__ int g_cursor[N_NODES];
__device__ int g_srcs[N_EDGES];
__device__ int g_bsum[SCAN_BLKS];

// ---------------- helpers ----------------
__device__ __forceinline__ uint32_t smem_u32(const void* p) {
    uint32_t a;
    asm("{ .reg .u64 t; cvta.to.shared.u64 t, %1; cvt.u32.u64 %0, t; }" : "=r"(a) : "l"(p));
    return a;
}
__device__ __forceinline__ int ld_idx(const void* p, long long i, int is64) {
    if (is64) return (int)((const long long*)p)[i];
    return ((const int*)p)[i];
}

// split 4 floats -> bf16 hi/lo packed as 2x uint2
__device__ __forceinline__ void split4(float4 v, uint2& hi, uint2& lo) {
    __nv_bfloat16 hx = __float2bfloat16_rn(v.x), hy = __float2bfloat16_rn(v.y);
    __nv_bfloat16 hz = __float2bfloat16_rn(v.z), hw = __float2bfloat16_rn(v.w);
    __nv_bfloat162 h0; h0.x = hx; h0.y = hy;
    __nv_bfloat162 h1; h1.x = hz; h1.y = hw;
    __nv_bfloat162 l0 = __floats2bfloat162_rn(v.x - __bfloat162float(hx),
                                              v.y - __bfloat162float(hy));
    __nv_bfloat162 l1 = __floats2bfloat162_rn(v.z - __bfloat162float(hz),
                                              v.w - __bfloat162float(hw));
    hi.x = *reinterpret_cast<uint32_t*>(&h0); hi.y = *reinterpret_cast<uint32_t*>(&h1);
    lo.x = *reinterpret_cast<uint32_t*>(&l0); lo.y = *reinterpret_cast<uint32_t*>(&l1);
}
__device__ __forceinline__ void cvt8(float4 v0, float4 v1, uint4& hi, uint4& lo) {
    uint2 h0, l0, h1, l1;
    split4(v0, h0, l0);
    split4(v1, h1, l1);
    hi = make_uint4(h0.x, h0.y, h1.x, h1.y);
    lo = make_uint4(l0.x, l0.y, l1.x, l1.y);
}

// ---------------- init: detect + zero rowptr + cnt/out + W convert ----------------
__global__ void init_kernel(const unsigned* __restrict__ ew,
                            float* __restrict__ out, const float* __restrict__ b_out,
                            const float* __restrict__ W1rel, const float* __restrict__ W1root,
                            const float* __restrict__ W2rel, const float* __restrict__ W2root) {
    int i = blockIdx.x * blockDim.x + threadIdx.x;
    if (i == 0) {
        unsigned o = 0;
#pragma unroll
        for (int k = 1; k < 64; k += 2) o |= ew[k];
        g_is64 = (o == 0) ? 1 : 0;
    }
    if (i < SCAN_N) g_rowptr[i] = 0;
    if (i < N_GRAPHS) { g_cnt[i] = 0; out[i] = b_out[0]; }
    if (i < 4 * 128 * DIM / 4) {                   // 16384 weight-convert threads
        int mat = i / (128 * DIM / 4);             // 0..3
        int off = (i % (128 * DIM / 4)) * 4;
        const float* src = (mat == 0) ? W1rel : (mat == 1) ? W1root
                         : (mat == 2) ? W2rel : W2root;
        int layer = mat >> 1;
        int half = mat & 1;                        // 0 rel -> rows 0-127, 1 root -> 128-255
        float4 v = *(const float4*)(src + off);
        uint2 hi, lo; split4(v, hi, lo);
        size_t dsto = (size_t)half * 128 * DIM + off;
        *(uint2*)(&g_whi[layer][dsto]) = hi;
        *(uint2*)(&g_wlo[layer][dsto]) = lo;
    }
}
__global__ void hist_count_kernel(const void* __restrict__ edges, const void* __restrict__ batch) {
    int e = blockIdx.x * blockDim.x + threadIdx.x;
    int is64 = g_is64;
    if (e < N_EDGES) {
        int dst = ld_idx(edges, (long long)N_EDGES + e, is64);
        atomicAdd(&g_rowptr[dst + 1], 1);
    }
    if (e < N_NODES) atomicAdd(&g_cnt[ld_idx(batch, e, is64)], 1);
}
// ---------------- scan: per-block inclusive (scan1) + apply block offsets (scan3) ----------------
__global__ __launch_bounds__(1024) void scan1_kernel() {
    __shared__ int sd[1024];
    int gid = blockIdx.x * 1024 + threadIdx.x;
    int v = (gid < SCAN_N) ? g_rowptr[gid] : 0;
    sd[threadIdx.x] = v;
    __syncthreads();
#pragma unroll
    for (int off = 1; off < 1024; off <<= 1) {
        int t = (threadIdx.x >= off) ? sd[threadIdx.x - off] : 0;
        __syncthreads();
        sd[threadIdx.x] += t;
        __syncthreads();
    }
    if (gid < SCAN_N) g_rowptr[gid] = sd[threadIdx.x];
    if (threadIdx.x == 1023) g_bsum[blockIdx.x] = sd[1023];
}
// scan3: each block warp-sums its exclusive bsum prefix, applies, seeds cursors
__global__ __launch_bounds__(1024) void scan3_kernel() {
    __shared__ int boff_s;
    if (threadIdx.x < 32) {
        int s = 0;
        for (int i = threadIdx.x; i < (int)blockIdx.x; i += 32) s += g_bsum[i];
#pragma unroll
        for (int o = 16; o; o >>= 1) s += __shfl_xor_sync(0xffffffffu, s, o);
        if (threadIdx.x == 0) boff_s = s;
    }
    __syncthreads();
    const int boff = boff_s;
    int gid = blockIdx.x * 1024 + threadIdx.x;
    if (gid < SCAN_N) {
        int v = g_rowptr[gid] + boff;
        g_rowptr[gid] = v;
        if (gid < N_NODES) g_cursor[gid] = v;   // seed fill cursor with row start
    }
}
__global__ void fill_kernel(const void* __restrict__ edges) {
    int e = blockIdx.x * blockDim.x + threadIdx.x;
    if (e < N_EDGES) {
        int is64 = g_is64;
        int src = ld_idx(edges, e, is64);
        int dst = ld_idx(edges, (long long)N_EDGES + e, is64);
        int pos = atomicAdd(&g_cursor[dst], 1);
        g_srcs[pos] = src;
    }
}

// ---------------- GEMM: 64-row A tile reused for BOTH weight halves, 2 CTAs/SM ----------------
#define PITCH_B 272
#define A_SZ    (64 * PITCH_B)             // 17408
#define B_SZ    (128 * PITCH_B)            // 34816
#define SMEM_BYTES (2 * A_SZ + 2 * B_SZ)   // 104448

__device__ __forceinline__ void ldsm_x4(uint32_t* r, uint32_t addr) {
    asm volatile("ldmatrix.sync.aligned.m8n8.x4.shared.b16 {%0,%1,%2,%3}, [%4];"
                 : "=r"(r[0]), "=r"(r[1]), "=r"(r[2]), "=r"(r[3]) : "r"(addr));
}
__device__ __forceinline__ void mma16816(float* d, const uint32_t* a, const uint32_t* b) {
    asm volatile(
        "mma.sync.aligned.m16n8k16.row.col.f32.bf16.bf16.f32 "
        "{%0,%1,%2,%3}, {%4,%5,%6,%7}, {%8,%9}, {%0,%1,%2,%3};"
        : "+f"(d[0]), "+f"(d[1]), "+f"(d[2]), "+f"(d[3])
        : "r"(a[0]), "r"(a[1]), "r"(a[2]), "r"(a[3]), "r"(b[0]), "r"(b[1]));
}
__device__ __forceinline__ void sts128u(uint32_t addr, uint4 v) {
    asm volatile("st.shared.v4.b32 [%0], {%1,%2,%3,%4};"
                 :: "r"(addr), "r"(v.x), "r"(v.y), "r"(v.z), "r"(v.w) : "memory");
}

// loop over both weight halves, reusing the A tile in SMEM
__device__ __forceinline__ void gemm_body(
    uint32_t sA, uint32_t sB, int layer,
    const float* __restrict__ bias, int row0,
    int tid, int wid, int lane)
{
    const int wm = wid >> 2;                   // 0..1  (M offset wm*32)
    const int wn = wid & 3;                    // 0..3  (N offset wn*32)
    const int t4 = lane >> 2;
    const int t2 = (lane & 3) * 2;

    const uint32_t aRowOff = (uint32_t)((lane & 15) * PITCH_B + (lane >> 4) * 16);
    const uint32_t bRowOff = (uint32_t)((wn * 32 + (lane & 7) + (lane >> 4) * 8) * PITCH_B
                                        + ((lane >> 3) & 1) * 16);

#pragma unroll
    for (int h = 0; h < 2; h++) {
        // sync: A stores (h=0) / prior mainloop ldsm (h=1) complete before B overwrite
        __syncthreads();
        const __nv_bfloat16* __restrict__ Bh = g_whi[layer] + (size_t)(h ? 128 : 0) * DIM;
        const __nv_bfloat16* __restrict__ Bl = g_wlo[layer] + (size_t)(h ? 128 : 0) * DIM;
#pragma unroll
        for (int i = 0; i < 8; i++) {
            int g = tid + i * 256;             // 0..2047
            int row = g >> 4;                  // 0..127
            int v = g & 15;
            size_t srco = (size_t)row * DIM + v * 8;
            uint32_t off = (uint32_t)(row * PITCH_B + v * 16);
            sts128u(sB + off,        *(const uint4*)(Bh + srco));
            sts128u(sB + B_SZ + off, *(const uint4*)(Bl + srco));
        }
        __syncthreads();

        float d[2][4][4];
#pragma unroll
        for (int i = 0; i < 2; i++)
#pragma unroll
            for (int j = 0; j < 4; j++)
#pragma unroll
                for (int q = 0; q < 4; q++) d[i][j][q] = 0.f;

#pragma unroll
        for (int ks = 0; ks < 8; ks++) {
            uint32_t aH[2][4], aL[2][4];
#pragma unroll
            for (int i = 0; i < 2; i++) {
                uint32_t base = (uint32_t)((wm * 32 + i * 16) * PITCH_B + ks * 32) + aRowOff;
                ldsm_x4(aH[i], sA + base);
                ldsm_x4(aL[i], sA + A_SZ + base);
            }
            uint32_t bH[4][2], bL[4][2];
#pragma unroll
            for (int jp = 0; jp < 2; jp++) {
                uint32_t base = (uint32_t)(jp * 16 * PITCH_B + ks * 32) + bRowOff;
                uint32_t r[4];
                ldsm_x4(r, sB + base);
                bH[jp * 2 + 0][0] = r[0]; bH[jp * 2 + 0][1] = r[1];
                bH[jp * 2 + 1][0] = r[2]; bH[jp * 2 + 1][1] = r[3];
                ldsm_x4(r, sB + B_SZ + base);
                bL[jp * 2 + 0][0] = r[0]; bL[jp * 2 + 0][1] = r[1];
                bL[jp * 2 + 1][0] = r[2]; bL[jp * 2 + 1][1] = r[3];
            }
#pragma unroll
            for (int i = 0; i < 2; i++)
#pragma unroll
                for (int j = 0; j < 4; j++) {
                    mma16816(d[i][j], aH[i], bH[j]);
                    mma16816(d[i][j], aL[i], bH[j]);
                    mma16816(d[i][j], aH[i], bL[j]);
                }
        }

        float* __restrict__ Out = h ? g_r : g_m;
#pragma unroll
        for (int i = 0; i < 2; i++) {
#pragma unroll
            for (int half = 0; half < 2; half++) {
                int grow = row0 + wm * 32 + i * 16 + t4 + half * 8;
                if (grow >= N_NODES) continue;
#pragma unroll
                for (int j = 0; j < 4; j++) {
                    int col = wn * 32 + j * 8 + t2;
                    float2 v = make_float2(d[i][j][half * 2], d[i][j][half * 2 + 1]);
                    if (h) { v.x += bias[col]; v.y += bias[col + 1]; }
                    *(float2*)(Out + (size_t)grow * DIM + col) = v;
                }
            }
        }
    }
}

// layer 1: A = fp32 x rows, convert in prologue (once per tile)
__global__ __launch_bounds__(256, 2) void gemm_cvt(
    const float* __restrict__ Xin, const float* __restrict__ bias)
{
    extern __shared__ char smem[];
    const uint32_t sA = smem_u32(smem);
    const uint32_t sB = sA + 2 * A_SZ;
    const int tid = threadIdx.x;
    const int wid = tid >> 5;
    const int lane = tid & 31;
    const int row0 = blockIdx.x * 64;

#pragma unroll
    for (int i = 0; i < 4; i++) {
        int g = tid + i * 256;             // 0..1023
        int row = g >> 4;                  // 0..63
        int e0 = (g & 15) * 8;
        int grow = row0 + row;
        float4 v0 = make_float4(0.f, 0.f, 0.f, 0.f), v1 = v0;
        if (grow < N_NODES) {
            v0 = *(const float4*)(Xin + (size_t)grow * DIM + e0);
            v1 = *(const float4*)(Xin + (size_t)grow * DIM + e0 + 4);
        }
        uint4 hi, lo; cvt8(v0, v1, hi, lo);
        uint32_t off = (uint32_t)(row * PITCH_B + e0 * 2);
        sts128u(sA + off, hi);
        sts128u(sA + A_SZ + off, lo);
    }
    gemm_body(sA, sB, 0, bias, row0, tid, wid, lane);
}

// layer 2: A = preconverted bf16 hi/lo (pure copy, once per tile)
__global__ __launch_bounds__(256, 2) void gemm_pre(const float* __restrict__ bias)
{
    extern __shared__ char smem[];
    const uint32_t sA = smem_u32(smem);
    const uint32_t sB = sA + 2 * A_SZ;
    const int tid = threadIdx.x;
    const int wid = tid >> 5;
    const int lane = tid & 31;
    const int row0 = blockIdx.x * 64;

#pragma unroll
    for (int i = 0; i < 4; i++) {
        int g = tid + i * 256;             // 0..1023
        int row = g >> 4;                  // 0..63
        int v = g & 15;
        size_t srco = (size_t)(row0 + row) * DIM + v * 8;
        uint32_t off = (uint32_t)(row * PITCH_B + v * 16);
        sts128u(sA + off,        *(const uint4*)(g_ahi + srco));
        sts128u(sA + A_SZ + off, *(const uint4*)(g_alo + srco));
    }
    gemm_body(sA, sB, 1, bias, row0, tid, wid, lane);
}

// ---------------- agg1: h1 = relu(root + sum msgs) -> bf16 hi/lo for gemm2 ----------------
__global__ __launch_bounds__(256) void agg1_kernel() {
    int node = (blockIdx.x * blockDim.x + threadIdx.x) >> 5;
    if (node >= N_NODES) return;
    const int lane = threadIdx.x & 31;
    const float4* __restrict__ M = (const float4*)g_m;
    int s = g_rowptr[node], e = g_rowptr[node + 1];
    float4 acc = make_float4(0.f, 0.f, 0.f, 0.f);
    for (int j = s; j < e; j++) {
        int src = g_srcs[j];
        float4 v = M[(size_t)src * 32 + lane];
        acc.x += v.x; acc.y += v.y; acc.z += v.z; acc.w += v.w;
    }
    float4 r = ((const float4*)g_r)[(size_t)node * 32 + lane];
    r.x = fmaxf(r.x + acc.x, 0.f); r.y = fmaxf(r.y + acc.y, 0.f);
    r.z = fmaxf(r.z + acc.z, 0.f); r.w = fmaxf(r.w + acc.w, 0.f);
    uint2 hi, lo; split4(r, hi, lo);
    ((uint2*)g_ahi)[(size_t)node * 32 + lane] = hi;
    ((uint2*)g_alo)[(size_t)node * 32 + lane] = lo;
}

// ---------------- layer-2 aggregate fused with mean-pool + head ----------------
__global__ __launch_bounds__(256) void agg2_pool_kernel(const void* __restrict__ batch,
                                                        const float* __restrict__ Wout,
                                                        float* __restrict__ out) {
    int node = (blockIdx.x * blockDim.x + threadIdx.x) >> 5;
    if (node >= N_NODES) return;
    const int lane = threadIdx.x & 31;
    const float4* __restrict__ M = (const float4*)g_m;
    int s = g_rowptr[node], e = g_rowptr[node + 1];
    float4 acc = make_float4(0.f, 0.f, 0.f, 0.f);
    for (int j = s; j < e; j++) {
        int src = g_srcs[j];
        float4 v = M[(size_t)src * 32 + lane];
        acc.x += v.x; acc.y += v.y; acc.z += v.z; acc.w += v.w;
    }
    float4 r = ((const float4*)g_r)[(size_t)node * 32 + lane];
    r.x = fmaxf(r.x + acc.x, 0.f); r.y = fmaxf(r.y + acc.y, 0.f);
    r.z = fmaxf(r.z + acc.z, 0.f); r.w = fmaxf(r.w + acc.w, 0.f);
    float4 w = ((const float4*)Wout)[lane];
    float sdot = r.x * w.x + r.y * w.y + r.z * w.z + r.w * w.w;
#pragma unroll
    for (int o = 16; o; o >>= 1) sdot += __shfl_xor_sync(0xffffffffu, sdot, o);
    if (lane == 0) {
        int gidx = ld_idx(batch, node, g_is64);
        int c = g_cnt[gidx]; if (c < 1) c = 1;
        atomicAdd(&out[gidx], sdot / (float)c);
    }
}

// ---------------- launcher (single stream, 9 launches; gemm_cvt 4th for ncu) ----------------
extern "C" void kernel_launch(void* const* d_in, const int* in_sizes, int n_in,
                              void* d_out, int out_size) {
    const float* x       = (const float*)d_in[0];
    const void*  edges   = d_in[1];
    const void*  batch   = d_in[2];
    const float* W1_rel  = (const float*)d_in[3];
    const float* W1_root = (const float*)d_in[4];
    const float* b1      = (const float*)d_in[5];
    const float* W2_rel  = (const float*)d_in[6];
    const float* W2_root = (const float*)d_in[7];
    const float* b2      = (const float*)d_in[8];
    const float* W_out   = (const float*)d_in[9];
    const float* b_out   = (const float*)d_in[10];
    float* out = (float*)d_out;

    cudaFuncSetAttribute(gemm_cvt, cudaFuncAttributeMaxDynamicSharedMemorySize, SMEM_BYTES);
    cudaFuncSetAttribute(gemm_pre, cudaFuncAttributeMaxDynamicSharedMemorySize, SMEM_BYTES);

    const int gemmBlks = PAD_NODES / 64;             // 782
    const int aggBlks = (N_NODES * 32 + 255) / 256;  // warp per node

    init_kernel<<<(SCAN_N + 255) / 256, 256>>>((const unsigned*)edges, out, b_out,
                                               W1_rel, W1_root, W2_rel, W2_root);
    hist_count_kernel<<<(N_EDGES + 255) / 256, 256>>>(edges, batch);
    scan1_kernel<<<SCAN_BLKS, 1024>>>();
    // gemm_cvt is independent of the CSR chain; placed 4th so ncu profiles it
    gemm_cvt<<<gemmBlks, 256, SMEM_BYTES>>>(x, b1);
    scan3_kernel<<<SCAN_BLKS, 1024>>>();
    fill_kernel<<<(N_EDGES + 255) / 256, 256>>>(edges);

    agg1_kernel<<<aggBlks, 256>>>();

    gemm_pre<<<gemmBlks, 256, SMEM_BYTES>>>(b2);
    agg2_pool_kernel<<<aggBlks, 256>>>(batch, W_out, out);
}